// round 10
// baseline (speedup 1.0000x reference)
#include <cuda_runtime.h>
#include <mma.h>
#include <math.h>

using namespace nvcuda;

// Problem dims
#define CB  8
#define CS  1300
#define CD  1080
#define CH  12
#define CDK 90
#define CDP 96
#define CFF 3240
#define CBS (CB*CS)

// ---------------- scratch ----------------
__device__ float g_x2 [(size_t)CBS*CD];
__device__ float g_qh [(size_t)CB*CH*CS*CDP];
__device__ float g_kh [(size_t)CB*CH*CS*CDP];
__device__ float g_vh [(size_t)CB*CH*CS*CDP];
__device__ float g_attn[(size_t)CBS*CD];
__device__ float g_res[(size_t)CBS*CD];
__device__ float g_h1 [(size_t)CBS*CFF];
__device__ float g_wqkv[(size_t)CD*CFF];
__device__ float g_bqkv[CFF];
__device__ float g_wr [(size_t)11664000];  // RN-rounded Wo|W1|W3|W2
#define WR_WO 0
#define WR_W1 1166400
#define WR_W3 4665600
#define WR_W2 8164800

enum { EPI_NONE=0, EPI_SCALE=1, EPI_BIAS=2, EPI_BIAS_RES=3, EPI_SWIGLU=4 };

__device__ __forceinline__ float rn_tf32(float x)
{
    float r;
    asm("cvt.rna.tf32.f32 %0, %1;" : "=f"(r) : "f"(x));
    return r;
}

__device__ __forceinline__ void cp_async16(float* smem, const float* gmem, bool pred)
{
    unsigned saddr = (unsigned)__cvta_generic_to_shared(smem);
    int sz = pred ? 16 : 0;
    asm volatile("cp.async.cg.shared.global [%0], [%1], 16, %2;\n"
                 :: "r"(saddr), "l"(gmem), "r"(sz));
}
__device__ __forceinline__ void cp_commit() { asm volatile("cp.async.commit_group;\n"); }

// raw tf32 mma m16n8k8 (A row-major, B col-major, f32 accum, in-place)
__device__ __forceinline__ void mma_tf32(float* d,
    unsigned a0, unsigned a1, unsigned a2, unsigned a3,
    unsigned b0, unsigned b1)
{
    asm volatile("mma.sync.aligned.m16n8k8.row.col.f32.tf32.tf32.f32 "
                 "{%0,%1,%2,%3}, {%4,%5,%6,%7}, {%8,%9}, {%0,%1,%2,%3};"
                 : "+f"(d[0]), "+f"(d[1]), "+f"(d[2]), "+f"(d[3])
                 : "r"(a0), "r"(a1), "r"(a2), "r"(a3), "r"(b0), "r"(b1));
}

// ------- TF32 GEMM: block 128x256, warp tile 64x64, 4-stage cp.async -------
#define ALD 24
#define BLD2 264
#define CLD 24
#define STG_A (128*ALD)            // 3072 floats
#define STG_B (16*BLD2)            // 4224 floats
#define STG_FT (STG_A+STG_B)       // 7296 floats/stage
#define SMEM_BYTES (4*STG_FT*4)    // 116736 B

template<int EPI>
__global__ __launch_bounds__(256, 1)
void gemm_tc(const float* __restrict__ A, int lda,
             const float* __restrict__ Bm, int ldb,
             float* __restrict__ C, int ldc,
             const float* __restrict__ bias,
             const float* __restrict__ aux, int ldx,
             int M, int N, int K)
{
    const int m0 = blockIdx.y * 128;
    const int n0 = blockIdx.x * 256;
    const int kEnd  = K;
    const int nIter = (kEnd + 15) >> 4;

    extern __shared__ __align__(16) float smem_dyn[];

    const int tid = threadIdx.x;
    const int wid = tid >> 5;
    const int lane = tid & 31;
    const int warp_m = wid & 1;     // 2 x 64 rows
    const int warp_n = wid >> 1;    // 4 x 64 cols

    const int aRow = tid >> 1;
    const int aC0  = (tid & 1) * 8;
    const int bRow = tid >> 4;          // 0..15
    const int bC0  = (tid & 15) * 16;   // 0..240

    const bool aRowOk = (m0 + aRow) < M;
    const float* aBase = A + (long)(m0 + aRow) * lda + aC0;
    const float* bBase = Bm + (long)bRow * ldb + n0 + bC0;

    wmma::fragment<wmma::accumulator, 16, 16, 8, float> acc[4][4];
    #pragma unroll
    for (int i = 0; i < 4; i++)
        #pragma unroll
        for (int j = 0; j < 4; j++) wmma::fill_fragment(acc[i][j], 0.f);

    auto issue = [&](int it, int buf) {
        const int k0 = it << 4;
        float* as = smem_dyn + buf * STG_FT;
        float* bs = as + STG_A;
        cp_async16(&as[aRow * ALD + aC0],     aBase + k0,     aRowOk && (k0 + aC0     < kEnd));
        cp_async16(&as[aRow * ALD + aC0 + 4], aBase + k0 + 4, aRowOk && (k0 + aC0 + 4 < kEnd));
        const bool rOk = (k0 + bRow) < kEnd;
        #pragma unroll
        for (int c = 0; c < 4; c++)
            cp_async16(&bs[bRow * BLD2 + bC0 + 4 * c],
                       bBase + (long)k0 * ldb + 4 * c,
                       rOk && (n0 + bC0 + 4 * c < N));
    };

    issue(0, 0); cp_commit();
    if (nIter > 1) { issue(1, 1); cp_commit(); }
    if (nIter > 2) { issue(2, 2); cp_commit(); }

    for (int it = 0; it < nIter; it++) {
        const int buf = it & 3;
        if (it + 2 < nIter)      asm volatile("cp.async.wait_group 2;\n");
        else if (it + 1 < nIter) asm volatile("cp.async.wait_group 1;\n");
        else                     asm volatile("cp.async.wait_group 0;\n");
        __syncthreads();
        if (it + 3 < nIter) { issue(it + 3, (it + 3) & 3); cp_commit(); }

        const float* as = smem_dyn + buf * STG_FT;
        const float* bs = as + STG_A;
        #pragma unroll
        for (int kk = 0; kk < 16; kk += 8) {
            wmma::fragment<wmma::matrix_a, 16, 16, 8, wmma::precision::tf32, wmma::row_major> af[4];
            #pragma unroll
            for (int i = 0; i < 4; i++)
                wmma::load_matrix_sync(af[i], &as[(warp_m * 64 + i * 16) * ALD + kk], ALD);
            #pragma unroll
            for (int j = 0; j < 4; j++) {
                wmma::fragment<wmma::matrix_b, 16, 16, 8, wmma::precision::tf32, wmma::row_major> bf;
                wmma::load_matrix_sync(bf, &bs[kk * BLD2 + warp_n * 64 + j * 16], BLD2);
                #pragma unroll
                for (int i = 0; i < 4; i++)
                    wmma::mma_sync(acc[i][j], af[i], bf, acc[i][j]);
            }
        }
    }
    __syncthreads();   // protect smem reuse by epilogue stage

    float* stage = &smem_dyn[wid * 16 * CLD];
    const int er  = lane >> 1;
    const int ec0 = (lane & 1) * 8;
    #pragma unroll
    for (int i = 0; i < 4; i++) {
        #pragma unroll
        for (int j = 0; j < 4; j++) {
            wmma::store_matrix_sync(stage, acc[i][j], CLD, wmma::mem_row_major);
            __syncwarp();
            const int gr = m0 + warp_m * 64 + i * 16 + er;
            const int gcb = n0 + warp_n * 64 + j * 16 + ec0;
            if (gr < M) {
                #pragma unroll
                for (int h4 = 0; h4 < 2; h4++) {
                    const int gc = gcb + h4 * 4;
                    if (gc + 3 < N) {
                        float4 v = *reinterpret_cast<const float4*>(&stage[er * CLD + ec0 + h4 * 4]);
                        if (EPI == EPI_BIAS) {
                            float4 bv = *reinterpret_cast<const float4*>(&bias[gc]);
                            v.x += bv.x; v.y += bv.y; v.z += bv.z; v.w += bv.w;
                        }
                        if (EPI == EPI_BIAS_RES) {
                            float4 bv = *reinterpret_cast<const float4*>(&bias[gc]);
                            float4 av = *reinterpret_cast<const float4*>(&aux[(long)gr * ldx + gc]);
                            v.x += bv.x + av.x; v.y += bv.y + av.y;
                            v.z += bv.z + av.z; v.w += bv.w + av.w;
                        }
                        if (EPI == EPI_SWIGLU) {
                            float4 bv = *reinterpret_cast<const float4*>(&bias[gc]);
                            float4 hv = *reinterpret_cast<const float4*>(&aux[(long)gr * ldx + gc]);
                            v.x = rn_tf32((hv.x / (1.f + __expf(-hv.x))) * (v.x + bv.x));
                            v.y = rn_tf32((hv.y / (1.f + __expf(-hv.y))) * (v.y + bv.y));
                            v.z = rn_tf32((hv.z / (1.f + __expf(-hv.z))) * (v.z + bv.z));
                            v.w = rn_tf32((hv.w / (1.f + __expf(-hv.w))) * (v.w + bv.w));
                        }
                        *reinterpret_cast<float4*>(&C[(long)gr * ldc + gc]) = v;
                    }
                }
            }
            __syncwarp();
        }
    }
}

// ---------------- flash attention: raw mma, register S/P/O, split K/V wait --
#define FQ 128
#define FN 64
#define QLD 100
#define FLASH_SMEM ((FQ*QLD + 2*FN*QLD)*4)   // 102400 B

__global__ __launch_bounds__(256, 2)
void flash_k(const float* __restrict__ qh, const float* __restrict__ kh,
             const float* __restrict__ vh, float* __restrict__ attn, float iscale)
{
    const int zi = blockIdx.y;
    const int iT = (int)gridDim.x - 1 - (int)blockIdx.x;  // heavy tiles first
    const int i0 = iT * FQ;
    const int tid = threadIdx.x;
    const int wid = tid >> 5;
    const int lane = tid & 31;
    const int g = lane >> 2;
    const int t = lane & 3;

    const float* Qp = qh + (long)zi * CS * CDP;
    const float* Kp = kh + (long)zi * CS * CDP;
    const float* Vp = vh + (long)zi * CS * CDP;

    extern __shared__ __align__(16) float sm[];
    float* Qs = sm;                  // [128][100]
    float* Ks = sm + FQ * QLD;       // [64][100]
    float* Vs = Ks + FN * QLD;       // [64][100]

    for (int tt = tid; tt < FQ * 24; tt += 256) {
        int r = tt / 24, c4 = (tt % 24) * 4;
        cp_async16(&Qs[r * QLD + c4], Qp + (long)(i0 + r) * CDP + c4, (i0 + r) < CS);
    }
    cp_commit();

    float oacc[12][4];
    #pragma unroll
    for (int n = 0; n < 12; n++)
        #pragma unroll
        for (int s = 0; s < 4; s++) oacc[n][s] = 0.f;
    float m0 = -1e30f, m1 = -1e30f, l0 = 0.f, l1 = 0.f;

    const int rw = wid * 16;
    const int row0 = i0 + rw + g;
    const int row1 = row0 + 8;
    const int jn = (min(CS, i0 + FQ) + FN - 1) / FN;

    asm volatile("cp.async.wait_group 0;\n");
    __syncthreads();

    for (int j = 0; j < jn; j++) {
        const int j0 = j * FN;
        __syncthreads();                          // all warps done with KV j-1
        // K group
        for (int tt = tid; tt < FN * 24; tt += 256) {
            int r = tt / 24, c4 = (tt % 24) * 4;
            cp_async16(&Ks[r * QLD + c4], Kp + (long)(j0 + r) * CDP + c4, (j0 + r) < CS);
        }
        cp_commit();
        // V group (stays in flight during S + softmax)
        for (int tt = tid; tt < FN * 24; tt += 256) {
            int r = tt / 24, c4 = (tt % 24) * 4;
            cp_async16(&Vs[r * QLD + c4], Vp + (long)(j0 + r) * CDP + c4, (j0 + r) < CS);
        }
        cp_commit();
        asm volatile("cp.async.wait_group 1;\n");  // K ready, V flying
        __syncthreads();

        const bool active = (j0 <= i0 + rw + 15);
        float sacc[8][4];

        if (active) {
            #pragma unroll
            for (int n = 0; n < 8; n++)
                #pragma unroll
                for (int s = 0; s < 4; s++) sacc[n][s] = 0.f;

            #pragma unroll
            for (int kf = 0; kf < 12; kf++) {
                const int kc = kf * 8;
                unsigned a0 = __float_as_uint(Qs[(rw + g)     * QLD + kc + t]);
                unsigned a1 = __float_as_uint(Qs[(rw + g + 8) * QLD + kc + t]);
                unsigned a2 = __float_as_uint(Qs[(rw + g)     * QLD + kc + t + 4]);
                unsigned a3 = __float_as_uint(Qs[(rw + g + 8) * QLD + kc + t + 4]);
                #pragma unroll
                for (int nf = 0; nf < 8; nf++) {
                    unsigned b0 = __float_as_uint(Ks[(nf * 8 + g) * QLD + kc + t]);
                    unsigned b1 = __float_as_uint(Ks[(nf * 8 + g) * QLD + kc + t + 4]);
                    mma_tf32(sacc[nf], a0, a1, a2, a3, b0, b1);
                }
            }

            // online softmax (registers + group shuffles)
            float rmax0 = -1e30f, rmax1 = -1e30f;
            #pragma unroll
            for (int nf = 0; nf < 8; nf++) {
                const int c0 = j0 + nf * 8 + 2 * t;
                float s0 = sacc[nf][0] * iscale; if (c0     > row0) s0 = -1e30f;
                float s1 = sacc[nf][1] * iscale; if (c0 + 1 > row0) s1 = -1e30f;
                float s2 = sacc[nf][2] * iscale; if (c0     > row1) s2 = -1e30f;
                float s3 = sacc[nf][3] * iscale; if (c0 + 1 > row1) s3 = -1e30f;
                sacc[nf][0] = s0; sacc[nf][1] = s1; sacc[nf][2] = s2; sacc[nf][3] = s3;
                rmax0 = fmaxf(rmax0, fmaxf(s0, s1));
                rmax1 = fmaxf(rmax1, fmaxf(s2, s3));
            }
            rmax0 = fmaxf(rmax0, __shfl_xor_sync(0xffffffffu, rmax0, 1));
            rmax0 = fmaxf(rmax0, __shfl_xor_sync(0xffffffffu, rmax0, 2));
            rmax1 = fmaxf(rmax1, __shfl_xor_sync(0xffffffffu, rmax1, 1));
            rmax1 = fmaxf(rmax1, __shfl_xor_sync(0xffffffffu, rmax1, 2));

            const float mn0 = fmaxf(m0, rmax0);
            const float mn1 = fmaxf(m1, rmax1);
            const float al0 = __expf(m0 - mn0);
            const float al1 = __expf(m1 - mn1);
            float ps0 = 0.f, ps1 = 0.f;
            #pragma unroll
            for (int nf = 0; nf < 8; nf++) {
                float p0 = rn_tf32(__expf(sacc[nf][0] - mn0));
                float p1 = rn_tf32(__expf(sacc[nf][1] - mn0));
                float p2 = rn_tf32(__expf(sacc[nf][2] - mn1));
                float p3 = rn_tf32(__expf(sacc[nf][3] - mn1));
                sacc[nf][0] = p0; sacc[nf][1] = p1; sacc[nf][2] = p2; sacc[nf][3] = p3;
                ps0 += p0 + p1; ps1 += p2 + p3;
            }
            ps0 += __shfl_xor_sync(0xffffffffu, ps0, 1);
            ps0 += __shfl_xor_sync(0xffffffffu, ps0, 2);
            ps1 += __shfl_xor_sync(0xffffffffu, ps1, 1);
            ps1 += __shfl_xor_sync(0xffffffffu, ps1, 2);
            l0 = l0 * al0 + ps0;  m0 = mn0;
            l1 = l1 * al1 + ps1;  m1 = mn1;

            #pragma unroll
            for (int n = 0; n < 12; n++) {
                oacc[n][0] *= al0; oacc[n][1] *= al0;
                oacc[n][2] *= al1; oacc[n][3] *= al1;
            }
        }

        asm volatile("cp.async.wait_group 0;\n");  // V ready
        __syncthreads();

        if (active) {
            const int srcA = (lane & ~3) | (t >> 1);
            const int srcB = srcA + 2;
            #pragma unroll
            for (int kf = 0; kf < 8; kf++) {
                float v00 = __shfl_sync(0xffffffffu, sacc[kf][0], srcA);
                float v01 = __shfl_sync(0xffffffffu, sacc[kf][1], srcA);
                float v20 = __shfl_sync(0xffffffffu, sacc[kf][2], srcA);
                float v21 = __shfl_sync(0xffffffffu, sacc[kf][3], srcA);
                float w00 = __shfl_sync(0xffffffffu, sacc[kf][0], srcB);
                float w01 = __shfl_sync(0xffffffffu, sacc[kf][1], srcB);
                float w20 = __shfl_sync(0xffffffffu, sacc[kf][2], srcB);
                float w21 = __shfl_sync(0xffffffffu, sacc[kf][3], srcB);
                unsigned a0 = __float_as_uint((t & 1) ? v01 : v00);
                unsigned a1 = __float_as_uint((t & 1) ? v21 : v20);
                unsigned a2 = __float_as_uint((t & 1) ? w01 : w00);
                unsigned a3 = __float_as_uint((t & 1) ? w21 : w20);
                #pragma unroll
                for (int nf = 0; nf < 12; nf++) {
                    unsigned b0 = __float_as_uint(Vs[(kf * 8 + t)     * QLD + nf * 8 + g]);
                    unsigned b1 = __float_as_uint(Vs[(kf * 8 + t + 4) * QLD + nf * 8 + g]);
                    mma_tf32(oacc[nf], a0, a1, a2, a3, b0, b1);
                }
            }
        }
    }

    const int b = zi / CH, h = zi - b * CH;
    const float il0 = (l0 > 0.f) ? 1.f / l0 : 0.f;
    const float il1 = (l1 > 0.f) ? 1.f / l1 : 0.f;
    #pragma unroll
    for (int nf = 0; nf < 12; nf++) {
        const int c0 = nf * 8 + 2 * t;
        if (c0 < CDK) {
            if (row0 < CS) {
                float2 v;
                v.x = rn_tf32(oacc[nf][0] * il0);
                v.y = rn_tf32(oacc[nf][1] * il0);
                *reinterpret_cast<float2*>(&attn[((long)b * CS + row0) * CD + h * CDK + c0]) = v;
            }
            if (row1 < CS) {
                float2 v;
                v.x = rn_tf32(oacc[nf][2] * il1);
                v.y = rn_tf32(oacc[nf][3] * il1);
                *reinterpret_cast<float2*>(&attn[((long)b * CS + row1) * CD + h * CDK + c0]) = v;
            }
        }
    }
}

// ---------------- RN-round copy ----------------
__global__ __launch_bounds__(256)
void round4_k(const float* __restrict__ s, float* __restrict__ d, int n4)
{
    int i = blockIdx.x * 256 + threadIdx.x;
    if (i < n4) {
        float4 v = reinterpret_cast<const float4*>(s)[i];
        v.x = rn_tf32(v.x); v.y = rn_tf32(v.y);
        v.z = rn_tf32(v.z); v.w = rn_tf32(v.w);
        reinterpret_cast<float4*>(d)[i] = v;
    }
}

// ---------------- pack Wq|Wk|Wv (RN) ----------------
__global__ __launch_bounds__(256)
void pack_qkv_k(const float* __restrict__ Wq, const float* __restrict__ Wk,
                const float* __restrict__ Wv,
                const float* __restrict__ bq, const float* __restrict__ bk,
                const float* __restrict__ bv,
                float* __restrict__ W, float* __restrict__ b)
{
    const int NW4 = CD * (CD / 4);
    long idx = (long)blockIdx.x * 256 + threadIdx.x;
    if (idx < NW4) {
        int r = (int)(idx / (CD / 4));
        int c = (int)(idx % (CD / 4)) * 4;
        float4 vq = *reinterpret_cast<const float4*>(Wq + (long)r * CD + c);
        float4 vk = *reinterpret_cast<const float4*>(Wk + (long)r * CD + c);
        float4 vv = *reinterpret_cast<const float4*>(Wv + (long)r * CD + c);
        vq.x=rn_tf32(vq.x); vq.y=rn_tf32(vq.y); vq.z=rn_tf32(vq.z); vq.w=rn_tf32(vq.w);
        vk.x=rn_tf32(vk.x); vk.y=rn_tf32(vk.y); vk.z=rn_tf32(vk.z); vk.w=rn_tf32(vk.w);
        vv.x=rn_tf32(vv.x); vv.y=rn_tf32(vv.y); vv.z=rn_tf32(vv.z); vv.w=rn_tf32(vv.w);
        *reinterpret_cast<float4*>(W + (long)r * CFF + c)          = vq;
        *reinterpret_cast<float4*>(W + (long)r * CFF + CD + c)     = vk;
        *reinterpret_cast<float4*>(W + (long)r * CFF + 2 * CD + c) = vv;
    } else if (idx < NW4 + CD / 4) {
        int c = (int)(idx - NW4) * 4;
        *reinterpret_cast<float4*>(b + c)          = *reinterpret_cast<const float4*>(bq + c);
        *reinterpret_cast<float4*>(b + CD + c)     = *reinterpret_cast<const float4*>(bk + c);
        *reinterpret_cast<float4*>(b + 2 * CD + c) = *reinterpret_cast<const float4*>(bv + c);
    }
}

// ---------------- layernorm (RN output) ----------------
__global__ __launch_bounds__(256)
void ln_k(const float* __restrict__ x, const float* __restrict__ g,
          const float* __restrict__ b, float* __restrict__ y)
{
    const long row = blockIdx.x;
    const float* xr = x + row * CD;
    float* yr = y + row * CD;

    float s = 0.f, s2 = 0.f;
    for (int i = threadIdx.x; i < CD; i += 256) {
        float v = xr[i]; s += v; s2 += v * v;
    }
    __shared__ float rs[8], rs2[8];
    __shared__ float bm, br;
    #pragma unroll
    for (int o = 16; o; o >>= 1) {
        s  += __shfl_xor_sync(0xffffffffu, s,  o);
        s2 += __shfl_xor_sync(0xffffffffu, s2, o);
    }
    if ((threadIdx.x & 31) == 0) { rs[threadIdx.x >> 5] = s; rs2[threadIdx.x >> 5] = s2; }
    __syncthreads();
    if (threadIdx.x < 8) {
        float a = rs[threadIdx.x], a2 = rs2[threadIdx.x];
        #pragma unroll
        for (int o = 4; o; o >>= 1) {
            a  += __shfl_xor_sync(0xffu, a,  o);
            a2 += __shfl_xor_sync(0xffu, a2, o);
        }
        if (threadIdx.x == 0) {
            float mean = a / CD;
            float var  = a2 / CD - mean * mean;
            bm = mean;
            br = rsqrtf(var + 1e-5f);
        }
    }
    __syncthreads();
    const float mean = bm, rstd = br;
    for (int i = threadIdx.x; i < CD; i += 256)
        yr[i] = rn_tf32((xr[i] - mean) * rstd * g[i] + b[i]);
}

// -------- RoPE + repack (RN) --------
__global__ __launch_bounds__(256)
void rope_repack_k(const float* __restrict__ qkv,
                   const float* __restrict__ ct, const float* __restrict__ st,
                   float* __restrict__ qh, float* __restrict__ kh,
                   float* __restrict__ vh)
{
    const long total = (long)CB * CH * CS * 48;
    long idx = (long)blockIdx.x * 256 + threadIdx.x;
    if (idx >= total) return;
    const int d = (int)(idx % 48);  idx /= 48;
    const int s = (int)(idx % CS);  idx /= CS;
    const int h = (int)(idx % CH);
    const int b = (int)(idx / CH);

    const long src = ((long)b * CS + s) * CFF + h * CDK;
    const long dst = (((long)b * CH + h) * CS + s) * CDP;

    if (d < 45) {
        const float c1 = ct[s * CDK + d],      s1 = st[s * CDK + d];
        const float c2 = ct[s * CDK + d + 45], s2 = st[s * CDK + d + 45];
        float q1 = qkv[src + d],          q2 = qkv[src + d + 45];
        qh[dst + d]      = rn_tf32(q1 * c1 - q2 * s1);
        qh[dst + d + 45] = rn_tf32(q2 * c2 + q1 * s2);
        float k1 = qkv[src + CD + d],     k2 = qkv[src + CD + d + 45];
        kh[dst + d]      = rn_tf32(k1 * c1 - k2 * s1);
        kh[dst + d + 45] = rn_tf32(k2 * c2 + k1 * s2);
        vh[dst + d]      = rn_tf32(qkv[src + 2 * CD + d]);
        vh[dst + d + 45] = rn_tf32(qkv[src + 2 * CD + d + 45]);
    } else {
        const int p = 90 + 2 * (d - 45);
        qh[dst + p] = 0.f; qh[dst + p + 1] = 0.f;
        kh[dst + p] = 0.f; kh[dst + p + 1] = 0.f;
        vh[dst + p] = 0.f; vh[dst + p + 1] = 0.f;
    }
}

// ---------------- host launch ----------------
extern "C" void kernel_launch(void* const* d_in, const int* in_sizes, int n_in,
                              void* d_out, int out_size)
{
    const float* x    = (const float*)d_in[0];
    const float* Wq   = (const float*)d_in[2];
    const float* bq   = (const float*)d_in[3];
    const float* Wk   = (const float*)d_in[4];
    const float* bk   = (const float*)d_in[5];
    const float* Wv   = (const float*)d_in[6];
    const float* bv   = (const float*)d_in[7];
    const float* Wo   = (const float*)d_in[8];
    const float* bo   = (const float*)d_in[9];
    const float* W1   = (const float*)d_in[10];
    const float* b1   = (const float*)d_in[11];
    const float* W2   = (const float*)d_in[12];
    const float* b2   = (const float*)d_in[13];
    const float* W3   = (const float*)d_in[14];
    const float* b3   = (const float*)d_in[15];
    const float* ln1g = (const float*)d_in[16];
    const float* ln1b = (const float*)d_in[17];
    const float* ln2g = (const float*)d_in[18];
    const float* ln2b = (const float*)d_in[19];
    const float* rc   = (const float*)d_in[20];
    const float* rs   = (const float*)d_in[21];
    float* out = (float*)d_out;

    float *x2, *qh, *kh, *vh, *attn, *res, *h1, *wqkv, *bqkv, *wr;
    cudaGetSymbolAddress((void**)&x2,   g_x2);
    cudaGetSymbolAddress((void**)&qh,   g_qh);
    cudaGetSymbolAddress((void**)&kh,   g_kh);
    cudaGetSymbolAddress((void**)&vh,   g_vh);
    cudaGetSymbolAddress((void**)&attn, g_attn);
    cudaGetSymbolAddress((void**)&res,  g_res);
    cudaGetSymbolAddress((void**)&h1,   g_h1);
    cudaGetSymbolAddress((void**)&wqkv, g_wqkv);
    cudaGetSymbolAddress((void**)&bqkv, g_bqkv);
    cudaGetSymbolAddress((void**)&wr,   g_wr);

    cudaFuncSetAttribute(gemm_tc<EPI_BIAS>,     cudaFuncAttributeMaxDynamicSharedMemorySize, SMEM_BYTES);
    cudaFuncSetAttribute(gemm_tc<EPI_BIAS_RES>, cudaFuncAttributeMaxDynamicSharedMemorySize, SMEM_BYTES);
    cudaFuncSetAttribute(gemm_tc<EPI_SWIGLU>,   cudaFuncAttributeMaxDynamicSharedMemorySize, SMEM_BYTES);
    cudaFuncSetAttribute(flash_k,               cudaFuncAttributeMaxDynamicSharedMemorySize, FLASH_SMEM);

    const float iscale = 1.f / sqrtf((float)CDK);

    // 0) RN-round weights + pack QKV
    round4_k<<<(291600 + 255) / 256, 256>>>(Wo, wr + WR_WO, 291600);
    round4_k<<<(874800 + 255) / 256, 256>>>(W1, wr + WR_W1, 874800);
    round4_k<<<(874800 + 255) / 256, 256>>>(W3, wr + WR_W3, 874800);
    round4_k<<<(874800 + 255) / 256, 256>>>(W2, wr + WR_W2, 874800);
    {
        int total = CD * (CD / 4) + CD / 4;
        pack_qkv_k<<<(total + 255) / 256, 256>>>(Wq, Wk, Wv, bq, bk, bv, wqkv, bqkv);
    }

    // 1) LN1
    ln_k<<<CBS, 256>>>(x, ln1g, ln1b, x2);

    // 2) fused QKV projection
    dim3 gQKV((CFF + 255) / 256, (CBS + 127) / 128, 1);
    gemm_tc<EPI_BIAS><<<gQKV, 256, SMEM_BYTES>>>(
        x2, CD, wqkv, CFF, h1, CFF, bqkv, nullptr, 0, CBS, CFF, CD);

    // 3) RoPE + repack
    {
        long total = (long)CB * CH * CS * 48;
        rope_repack_k<<<(unsigned)((total + 255) / 256), 256>>>(h1, rc, rs, qh, kh, vh);
    }

    // 4) flash attention (register-resident, split K/V wait)
    {
        dim3 g((CS + FQ - 1) / FQ, CB * CH);
        flash_k<<<g, 256, FLASH_SMEM>>>(qh, kh, vh, attn, iscale);
    }

    // 5) O-projection + bias + residual(x)
    dim3 gD((CD + 255) / 256, (CBS + 127) / 128, 1);
    gemm_tc<EPI_BIAS_RES><<<gD, 256, SMEM_BYTES>>>(
        attn, CD, wr + WR_WO, CD, res, CD, bo, x, CD, CBS, CD, CD);

    // 6) LN2
    ln_k<<<CBS, 256>>>(res, ln2g, ln2b, x2);

    // 7) h1 = x2@W1 + b1
    dim3 gF((CFF + 255) / 256, (CBS + 127) / 128, 1);
    gemm_tc<EPI_BIAS><<<gF, 256, SMEM_BYTES>>>(
        x2, CD, wr + WR_W1, CFF, h1, CFF, b1, nullptr, 0, CBS, CFF, CD);

    // 8) h1 = silu(h1) * (x2@W3 + b3)
    gemm_tc<EPI_SWIGLU><<<gF, 256, SMEM_BYTES>>>(
        x2, CD, wr + WR_W3, CFF, h1, CFF, b3, h1, CFF, CBS, CFF, CD);

    // 9) out = res + h1@W2 + b2
    gemm_tc<EPI_BIAS_RES><<<gD, 256, SMEM_BYTES>>>(
        h1, CFF, wr + WR_W2, CD, out, CD, b2, res, CD, CBS, CD, CFF);
}

// round 11
// speedup vs baseline: 1.0225x; 1.0225x over previous
#include <cuda_runtime.h>
#include <mma.h>
#include <math.h>

using namespace nvcuda;

// Problem dims
#define CB  8
#define CS  1300
#define CD  1080
#define CH  12
#define CDK 90
#define CDP 96
#define CFF 3240
#define CBS (CB*CS)

// ---------------- scratch ----------------
__device__ float g_x2 [(size_t)CBS*CD];
__device__ float g_qh [(size_t)CB*CH*CS*CDP];
__device__ float g_kh [(size_t)CB*CH*CS*CDP];
__device__ float g_vh [(size_t)CB*CH*CS*CDP];
__device__ float g_attn[(size_t)CBS*CD];
__device__ float g_res[(size_t)CBS*CD];
__device__ float g_h1 [(size_t)CBS*CFF];
__device__ float g_wqkv[(size_t)CD*CFF];
__device__ float g_bqkv[CFF];
__device__ float g_wr [(size_t)11664000];  // RN-rounded Wo|W1|W3|W2
#define WR_WO 0
#define WR_W1 1166400
#define WR_W3 4665600
#define WR_W2 8164800

enum { EPI_NONE=0, EPI_SCALE=1, EPI_BIAS=2, EPI_BIAS_RES=3, EPI_SWIGLU=4 };

__device__ __forceinline__ float rn_tf32(float x)
{
    float r;
    asm("cvt.rna.tf32.f32 %0, %1;" : "=f"(r) : "f"(x));
    return r;
}

__device__ __forceinline__ void cp_async16(float* smem, const float* gmem, bool pred)
{
    unsigned saddr = (unsigned)__cvta_generic_to_shared(smem);
    int sz = pred ? 16 : 0;
    asm volatile("cp.async.cg.shared.global [%0], [%1], 16, %2;\n"
                 :: "r"(saddr), "l"(gmem), "r"(sz));
}
__device__ __forceinline__ void cp_commit() { asm volatile("cp.async.commit_group;\n"); }

// raw tf32 mma m16n8k8 (A row-major, B col-major, f32 accum, in-place)
__device__ __forceinline__ void mma_tf32(float* d,
    unsigned a0, unsigned a1, unsigned a2, unsigned a3,
    unsigned b0, unsigned b1)
{
    asm volatile("mma.sync.aligned.m16n8k8.row.col.f32.tf32.tf32.f32 "
                 "{%0,%1,%2,%3}, {%4,%5,%6,%7}, {%8,%9}, {%0,%1,%2,%3};"
                 : "+f"(d[0]), "+f"(d[1]), "+f"(d[2]), "+f"(d[3])
                 : "r"(a0), "r"(a1), "r"(a2), "r"(a3), "r"(b0), "r"(b1));
}

// ---- TF32 GEMM (R9 winner): 128x128, 32x64 warp tile, 4-stage, 2 CTAs/SM ---
#define ALD 24
#define BLD 136
#define CLD 24
#define STG_F (128*ALD)
#define SMEM_BYTES (4*STG_F*2*4)   // 98304 B

template<int EPI>
__global__ __launch_bounds__(256, 2)
void gemm_tc(const float* __restrict__ A, int lda,
             const float* __restrict__ Bm, int ldb,
             float* __restrict__ C, int ldc,
             const float* __restrict__ bias,
             const float* __restrict__ aux, int ldx,
             int M, int N, int K)
{
    const int m0 = blockIdx.y * 128;
    const int n0 = blockIdx.x * 128;
    const int kEnd  = K;
    const int nIter = (kEnd + 15) >> 4;

    extern __shared__ __align__(16) float smem_dyn[];
    float* As = smem_dyn;
    float* Bs = smem_dyn + 4 * STG_F;

    const int tid = threadIdx.x;
    const int wid = tid >> 5;
    const int lane = tid & 31;
    const int warp_m = wid & 3;
    const int warp_n = wid >> 2;

    const int aRow = tid >> 1;
    const int aC0  = (tid & 1) * 8;
    const int bRowN = tid >> 4;
    const int bC0N  = (tid & 15) * 8;

    const bool aRowOk = (m0 + aRow) < M;
    const float* aBase = A + (long)(m0 + aRow) * lda + aC0;
    const float* bBaseN = Bm + (long)bRowN * ldb + n0 + bC0N;
    const bool bColOkN = (n0 + bC0N) < N;
    const bool bColOkN4 = (n0 + bC0N + 4) < N;

    wmma::fragment<wmma::accumulator, 16, 16, 8, float> acc[2][4];
    #pragma unroll
    for (int i = 0; i < 2; i++)
        #pragma unroll
        for (int j = 0; j < 4; j++) wmma::fill_fragment(acc[i][j], 0.f);

    auto issue = [&](int it, int buf) {
        const int k0 = it << 4;
        float* as = As + buf * STG_F;
        float* bs = Bs + buf * STG_F;
        cp_async16(&as[aRow * ALD + aC0],     aBase + k0,     aRowOk && (k0 + aC0     < kEnd));
        cp_async16(&as[aRow * ALD + aC0 + 4], aBase + k0 + 4, aRowOk && (k0 + aC0 + 4 < kEnd));
        const bool rOk = (k0 + bRowN) < kEnd;
        cp_async16(&bs[bRowN * BLD + bC0N],     bBaseN + (long)k0 * ldb,     rOk && bColOkN);
        cp_async16(&bs[bRowN * BLD + bC0N + 4], bBaseN + (long)k0 * ldb + 4, rOk && bColOkN4);
    };

    issue(0, 0); cp_commit();
    if (nIter > 1) { issue(1, 1); cp_commit(); }
    if (nIter > 2) { issue(2, 2); cp_commit(); }

    for (int it = 0; it < nIter; it++) {
        const int buf = it & 3;
        if (it + 2 < nIter)      asm volatile("cp.async.wait_group 2;\n");
        else if (it + 1 < nIter) asm volatile("cp.async.wait_group 1;\n");
        else                     asm volatile("cp.async.wait_group 0;\n");
        __syncthreads();
        if (it + 3 < nIter) { issue(it + 3, (it + 3) & 3); cp_commit(); }

        const float* as = As + buf * STG_F;
        const float* bs = Bs + buf * STG_F;
        #pragma unroll
        for (int kk = 0; kk < 16; kk += 8) {
            wmma::fragment<wmma::matrix_a, 16, 16, 8, wmma::precision::tf32, wmma::row_major> af[2];
            #pragma unroll
            for (int i = 0; i < 2; i++)
                wmma::load_matrix_sync(af[i], &as[(warp_m * 32 + i * 16) * ALD + kk], ALD);
            #pragma unroll
            for (int j = 0; j < 4; j++) {
                wmma::fragment<wmma::matrix_b, 16, 16, 8, wmma::precision::tf32, wmma::row_major> bf;
                wmma::load_matrix_sync(bf, &bs[kk * BLD + warp_n * 64 + j * 16], BLD);
                wmma::mma_sync(acc[0][j], af[0], bf, acc[0][j]);
                wmma::mma_sync(acc[1][j], af[1], bf, acc[1][j]);
            }
        }
    }
    __syncthreads();   // protect smem reuse by epilogue stage

    float* stage = &As[wid * 16 * CLD];
    const int er  = lane >> 1;
    const int ec0 = (lane & 1) * 8;
    #pragma unroll
    for (int i = 0; i < 2; i++) {
        #pragma unroll
        for (int j = 0; j < 4; j++) {
            wmma::store_matrix_sync(stage, acc[i][j], CLD, wmma::mem_row_major);
            __syncwarp();
            const int gr = m0 + warp_m * 32 + i * 16 + er;
            const int gcb = n0 + warp_n * 64 + j * 16 + ec0;
            if (gr < M) {
                #pragma unroll
                for (int h4 = 0; h4 < 2; h4++) {
                    const int gc = gcb + h4 * 4;
                    if (gc + 3 < N) {
                        float4 v = *reinterpret_cast<const float4*>(&stage[er * CLD + ec0 + h4 * 4]);
                        if (EPI == EPI_BIAS) {
                            float4 bv = *reinterpret_cast<const float4*>(&bias[gc]);
                            v.x += bv.x; v.y += bv.y; v.z += bv.z; v.w += bv.w;
                        }
                        if (EPI == EPI_BIAS_RES) {
                            float4 bv = *reinterpret_cast<const float4*>(&bias[gc]);
                            float4 av = *reinterpret_cast<const float4*>(&aux[(long)gr * ldx + gc]);
                            v.x += bv.x + av.x; v.y += bv.y + av.y;
                            v.z += bv.z + av.z; v.w += bv.w + av.w;
                        }
                        if (EPI == EPI_SWIGLU) {
                            float4 bv = *reinterpret_cast<const float4*>(&bias[gc]);
                            float4 hv = *reinterpret_cast<const float4*>(&aux[(long)gr * ldx + gc]);
                            v.x = rn_tf32((hv.x / (1.f + __expf(-hv.x))) * (v.x + bv.x));
                            v.y = rn_tf32((hv.y / (1.f + __expf(-hv.y))) * (v.y + bv.y));
                            v.z = rn_tf32((hv.z / (1.f + __expf(-hv.z))) * (v.z + bv.z));
                            v.w = rn_tf32((hv.w / (1.f + __expf(-hv.w))) * (v.w + bv.w));
                        }
                        *reinterpret_cast<float4*>(&C[(long)gr * ldc + gc]) = v;
                    }
                }
            }
            __syncwarp();
        }
    }
}

// ---------------- flash attention: raw mma, register S/P/O, split K/V wait --
#define FQ 128
#define FN 64
#define QLD 100
#define FLASH_SMEM ((FQ*QLD + 2*FN*QLD)*4)   // 102400 B

__global__ __launch_bounds__(256, 2)
void flash_k(const float* __restrict__ qh, const float* __restrict__ kh,
             const float* __restrict__ vh, float* __restrict__ attn, float iscale)
{
    const int zi = blockIdx.y;
    const int iT = (int)gridDim.x - 1 - (int)blockIdx.x;  // heavy tiles first
    const int i0 = iT * FQ;
    const int tid = threadIdx.x;
    const int wid = tid >> 5;
    const int lane = tid & 31;
    const int g = lane >> 2;
    const int t = lane & 3;

    const float* Qp = qh + (long)zi * CS * CDP;
    const float* Kp = kh + (long)zi * CS * CDP;
    const float* Vp = vh + (long)zi * CS * CDP;

    extern __shared__ __align__(16) float sm[];
    float* Qs = sm;                  // [128][100]
    float* Ks = sm + FQ * QLD;       // [64][100]
    float* Vs = Ks + FN * QLD;       // [64][100]

    for (int tt = tid; tt < FQ * 24; tt += 256) {
        int r = tt / 24, c4 = (tt % 24) * 4;
        cp_async16(&Qs[r * QLD + c4], Qp + (long)(i0 + r) * CDP + c4, (i0 + r) < CS);
    }
    cp_commit();

    float oacc[12][4];
    #pragma unroll
    for (int n = 0; n < 12; n++)
        #pragma unroll
        for (int s = 0; s < 4; s++) oacc[n][s] = 0.f;
    float m0 = -1e30f, m1 = -1e30f, l0 = 0.f, l1 = 0.f;

    const int rw = wid * 16;
    const int row0 = i0 + rw + g;
    const int row1 = row0 + 8;
    const int jn = (min(CS, i0 + FQ) + FN - 1) / FN;

    asm volatile("cp.async.wait_group 0;\n");
    __syncthreads();

    for (int j = 0; j < jn; j++) {
        const int j0 = j * FN;
        __syncthreads();                          // all warps done with KV j-1
        // K group
        for (int tt = tid; tt < FN * 24; tt += 256) {
            int r = tt / 24, c4 = (tt % 24) * 4;
            cp_async16(&Ks[r * QLD + c4], Kp + (long)(j0 + r) * CDP + c4, (j0 + r) < CS);
        }
        cp_commit();
        // V group (stays in flight during S + softmax)
        for (int tt = tid; tt < FN * 24; tt += 256) {
            int r = tt / 24, c4 = (tt % 24) * 4;
            cp_async16(&Vs[r * QLD + c4], Vp + (long)(j0 + r) * CDP + c4, (j0 + r) < CS);
        }
        cp_commit();
        asm volatile("cp.async.wait_group 1;\n");  // K ready, V flying
        __syncthreads();

        const bool active = (j0 <= i0 + rw + 15);
        float sacc[8][4];

        if (active) {
            #pragma unroll
            for (int n = 0; n < 8; n++)
                #pragma unroll
                for (int s = 0; s < 4; s++) sacc[n][s] = 0.f;

            #pragma unroll
            for (int kf = 0; kf < 12; kf++) {
                const int kc = kf * 8;
                unsigned a0 = __float_as_uint(Qs[(rw + g)     * QLD + kc + t]);
                unsigned a1 = __float_as_uint(Qs[(rw + g + 8) * QLD + kc + t]);
                unsigned a2 = __float_as_uint(Qs[(rw + g)     * QLD + kc + t + 4]);
                unsigned a3 = __float_as_uint(Qs[(rw + g + 8) * QLD + kc + t + 4]);
                #pragma unroll
                for (int nf = 0; nf < 8; nf++) {
                    unsigned b0 = __float_as_uint(Ks[(nf * 8 + g) * QLD + kc + t]);
                    unsigned b1 = __float_as_uint(Ks[(nf * 8 + g) * QLD + kc + t + 4]);
                    mma_tf32(sacc[nf], a0, a1, a2, a3, b0, b1);
                }
            }

            // online softmax (registers + group shuffles)
            float rmax0 = -1e30f, rmax1 = -1e30f;
            #pragma unroll
            for (int nf = 0; nf < 8; nf++) {
                const int c0 = j0 + nf * 8 + 2 * t;
                float s0 = sacc[nf][0] * iscale; if (c0     > row0) s0 = -1e30f;
                float s1 = sacc[nf][1] * iscale; if (c0 + 1 > row0) s1 = -1e30f;
                float s2 = sacc[nf][2] * iscale; if (c0     > row1) s2 = -1e30f;
                float s3 = sacc[nf][3] * iscale; if (c0 + 1 > row1) s3 = -1e30f;
                sacc[nf][0] = s0; sacc[nf][1] = s1; sacc[nf][2] = s2; sacc[nf][3] = s3;
                rmax0 = fmaxf(rmax0, fmaxf(s0, s1));
                rmax1 = fmaxf(rmax1, fmaxf(s2, s3));
            }
            rmax0 = fmaxf(rmax0, __shfl_xor_sync(0xffffffffu, rmax0, 1));
            rmax0 = fmaxf(rmax0, __shfl_xor_sync(0xffffffffu, rmax0, 2));
            rmax1 = fmaxf(rmax1, __shfl_xor_sync(0xffffffffu, rmax1, 1));
            rmax1 = fmaxf(rmax1, __shfl_xor_sync(0xffffffffu, rmax1, 2));

            const float mn0 = fmaxf(m0, rmax0);
            const float mn1 = fmaxf(m1, rmax1);
            const float al0 = __expf(m0 - mn0);
            const float al1 = __expf(m1 - mn1);
            float ps0 = 0.f, ps1 = 0.f;
            #pragma unroll
            for (int nf = 0; nf < 8; nf++) {
                float p0 = rn_tf32(__expf(sacc[nf][0] - mn0));
                float p1 = rn_tf32(__expf(sacc[nf][1] - mn0));
                float p2 = rn_tf32(__expf(sacc[nf][2] - mn1));
                float p3 = rn_tf32(__expf(sacc[nf][3] - mn1));
                sacc[nf][0] = p0; sacc[nf][1] = p1; sacc[nf][2] = p2; sacc[nf][3] = p3;
                ps0 += p0 + p1; ps1 += p2 + p3;
            }
            ps0 += __shfl_xor_sync(0xffffffffu, ps0, 1);
            ps0 += __shfl_xor_sync(0xffffffffu, ps0, 2);
            ps1 += __shfl_xor_sync(0xffffffffu, ps1, 1);
            ps1 += __shfl_xor_sync(0xffffffffu, ps1, 2);
            l0 = l0 * al0 + ps0;  m0 = mn0;
            l1 = l1 * al1 + ps1;  m1 = mn1;

            #pragma unroll
            for (int n = 0; n < 12; n++) {
                oacc[n][0] *= al0; oacc[n][1] *= al0;
                oacc[n][2] *= al1; oacc[n][3] *= al1;
            }
        }

        asm volatile("cp.async.wait_group 0;\n");  // V ready
        __syncthreads();

        if (active) {
            const int srcA = (lane & ~3) | (t >> 1);
            const int srcB = srcA + 2;
            #pragma unroll
            for (int kf = 0; kf < 8; kf++) {
                float v00 = __shfl_sync(0xffffffffu, sacc[kf][0], srcA);
                float v01 = __shfl_sync(0xffffffffu, sacc[kf][1], srcA);
                float v20 = __shfl_sync(0xffffffffu, sacc[kf][2], srcA);
                float v21 = __shfl_sync(0xffffffffu, sacc[kf][3], srcA);
                float w00 = __shfl_sync(0xffffffffu, sacc[kf][0], srcB);
                float w01 = __shfl_sync(0xffffffffu, sacc[kf][1], srcB);
                float w20 = __shfl_sync(0xffffffffu, sacc[kf][2], srcB);
                float w21 = __shfl_sync(0xffffffffu, sacc[kf][3], srcB);
                unsigned a0 = __float_as_uint((t & 1) ? v01 : v00);
                unsigned a1 = __float_as_uint((t & 1) ? v21 : v20);
                unsigned a2 = __float_as_uint((t & 1) ? w01 : w00);
                unsigned a3 = __float_as_uint((t & 1) ? w21 : w20);
                #pragma unroll
                for (int nf = 0; nf < 12; nf++) {
                    unsigned b0 = __float_as_uint(Vs[(kf * 8 + t)     * QLD + nf * 8 + g]);
                    unsigned b1 = __float_as_uint(Vs[(kf * 8 + t + 4) * QLD + nf * 8 + g]);
                    mma_tf32(oacc[nf], a0, a1, a2, a3, b0, b1);
                }
            }
        }
    }

    const int b = zi / CH, h = zi - b * CH;
    const float il0 = (l0 > 0.f) ? 1.f / l0 : 0.f;
    const float il1 = (l1 > 0.f) ? 1.f / l1 : 0.f;
    #pragma unroll
    for (int nf = 0; nf < 12; nf++) {
        const int c0 = nf * 8 + 2 * t;
        if (c0 < CDK) {
            if (row0 < CS) {
                float2 v;
                v.x = rn_tf32(oacc[nf][0] * il0);
                v.y = rn_tf32(oacc[nf][1] * il0);
                *reinterpret_cast<float2*>(&attn[((long)b * CS + row0) * CD + h * CDK + c0]) = v;
            }
            if (row1 < CS) {
                float2 v;
                v.x = rn_tf32(oacc[nf][2] * il1);
                v.y = rn_tf32(oacc[nf][3] * il1);
                *reinterpret_cast<float2*>(&attn[((long)b * CS + row1) * CD + h * CDK + c0]) = v;
            }
        }
    }
}

// ---------------- RN-round copy ----------------
__global__ __launch_bounds__(256)
void round4_k(const float* __restrict__ s, float* __restrict__ d, int n4)
{
    int i = blockIdx.x * 256 + threadIdx.x;
    if (i < n4) {
        float4 v = reinterpret_cast<const float4*>(s)[i];
        v.x = rn_tf32(v.x); v.y = rn_tf32(v.y);
        v.z = rn_tf32(v.z); v.w = rn_tf32(v.w);
        reinterpret_cast<float4*>(d)[i] = v;
    }
}

// ---------------- pack Wq|Wk|Wv (RN) ----------------
__global__ __launch_bounds__(256)
void pack_qkv_k(const float* __restrict__ Wq, const float* __restrict__ Wk,
                const float* __restrict__ Wv,
                const float* __restrict__ bq, const float* __restrict__ bk,
                const float* __restrict__ bv,
                float* __restrict__ W, float* __restrict__ b)
{
    const int NW4 = CD * (CD / 4);
    long idx = (long)blockIdx.x * 256 + threadIdx.x;
    if (idx < NW4) {
        int r = (int)(idx / (CD / 4));
        int c = (int)(idx % (CD / 4)) * 4;
        float4 vq = *reinterpret_cast<const float4*>(Wq + (long)r * CD + c);
        float4 vk = *reinterpret_cast<const float4*>(Wk + (long)r * CD + c);
        float4 vv = *reinterpret_cast<const float4*>(Wv + (long)r * CD + c);
        vq.x=rn_tf32(vq.x); vq.y=rn_tf32(vq.y); vq.z=rn_tf32(vq.z); vq.w=rn_tf32(vq.w);
        vk.x=rn_tf32(vk.x); vk.y=rn_tf32(vk.y); vk.z=rn_tf32(vk.z); vk.w=rn_tf32(vk.w);
        vv.x=rn_tf32(vv.x); vv.y=rn_tf32(vv.y); vv.z=rn_tf32(vv.z); vv.w=rn_tf32(vv.w);
        *reinterpret_cast<float4*>(W + (long)r * CFF + c)          = vq;
        *reinterpret_cast<float4*>(W + (long)r * CFF + CD + c)     = vk;
        *reinterpret_cast<float4*>(W + (long)r * CFF + 2 * CD + c) = vv;
    } else if (idx < NW4 + CD / 4) {
        int c = (int)(idx - NW4) * 4;
        *reinterpret_cast<float4*>(b + c)          = *reinterpret_cast<const float4*>(bq + c);
        *reinterpret_cast<float4*>(b + CD + c)     = *reinterpret_cast<const float4*>(bk + c);
        *reinterpret_cast<float4*>(b + 2 * CD + c) = *reinterpret_cast<const float4*>(bv + c);
    }
}

// ---------------- layernorm (RN output) ----------------
__global__ __launch_bounds__(256)
void ln_k(const float* __restrict__ x, const float* __restrict__ g,
          const float* __restrict__ b, float* __restrict__ y)
{
    const long row = blockIdx.x;
    const float* xr = x + row * CD;
    float* yr = y + row * CD;

    float s = 0.f, s2 = 0.f;
    for (int i = threadIdx.x; i < CD; i += 256) {
        float v = xr[i]; s += v; s2 += v * v;
    }
    __shared__ float rs[8], rs2[8];
    __shared__ float bm, br;
    #pragma unroll
    for (int o = 16; o; o >>= 1) {
        s  += __shfl_xor_sync(0xffffffffu, s,  o);
        s2 += __shfl_xor_sync(0xffffffffu, s2, o);
    }
    if ((threadIdx.x & 31) == 0) { rs[threadIdx.x >> 5] = s; rs2[threadIdx.x >> 5] = s2; }
    __syncthreads();
    if (threadIdx.x < 8) {
        float a = rs[threadIdx.x], a2 = rs2[threadIdx.x];
        #pragma unroll
        for (int o = 4; o; o >>= 1) {
            a  += __shfl_xor_sync(0xffu, a,  o);
            a2 += __shfl_xor_sync(0xffu, a2, o);
        }
        if (threadIdx.x == 0) {
            float mean = a / CD;
            float var  = a2 / CD - mean * mean;
            bm = mean;
            br = rsqrtf(var + 1e-5f);
        }
    }
    __syncthreads();
    const float mean = bm, rstd = br;
    for (int i = threadIdx.x; i < CD; i += 256)
        yr[i] = rn_tf32((xr[i] - mean) * rstd * g[i] + b[i]);
}

// -------- RoPE + repack (RN) --------
__global__ __launch_bounds__(256)
void rope_repack_k(const float* __restrict__ qkv,
                   const float* __restrict__ ct, const float* __restrict__ st,
                   float* __restrict__ qh, float* __restrict__ kh,
                   float* __restrict__ vh)
{
    const long total = (long)CB * CH * CS * 48;
    long idx = (long)blockIdx.x * 256 + threadIdx.x;
    if (idx >= total) return;
    const int d = (int)(idx % 48);  idx /= 48;
    const int s = (int)(idx % CS);  idx /= CS;
    const int h = (int)(idx % CH);
    const int b = (int)(idx / CH);

    const long src = ((long)b * CS + s) * CFF + h * CDK;
    const long dst = (((long)b * CH + h) * CS + s) * CDP;

    if (d < 45) {
        const float c1 = ct[s * CDK + d],      s1 = st[s * CDK + d];
        const float c2 = ct[s * CDK + d + 45], s2 = st[s * CDK + d + 45];
        float q1 = qkv[src + d],          q2 = qkv[src + d + 45];
        qh[dst + d]      = rn_tf32(q1 * c1 - q2 * s1);
        qh[dst + d + 45] = rn_tf32(q2 * c2 + q1 * s2);
        float k1 = qkv[src + CD + d],     k2 = qkv[src + CD + d + 45];
        kh[dst + d]      = rn_tf32(k1 * c1 - k2 * s1);
        kh[dst + d + 45] = rn_tf32(k2 * c2 + k1 * s2);
        vh[dst + d]      = rn_tf32(qkv[src + 2 * CD + d]);
        vh[dst + d + 45] = rn_tf32(qkv[src + 2 * CD + d + 45]);
    } else {
        const int p = 90 + 2 * (d - 45);
        qh[dst + p] = 0.f; qh[dst + p + 1] = 0.f;
        kh[dst + p] = 0.f; kh[dst + p + 1] = 0.f;
        vh[dst + p] = 0.f; vh[dst + p + 1] = 0.f;
    }
}

// ---------------- host launch ----------------
extern "C" void kernel_launch(void* const* d_in, const int* in_sizes, int n_in,
                              void* d_out, int out_size)
{
    const float* x    = (const float*)d_in[0];
    const float* Wq   = (const float*)d_in[2];
    const float* bq   = (const float*)d_in[3];
    const float* Wk   = (const float*)d_in[4];
    const float* bk   = (const float*)d_in[5];
    const float* Wv   = (const float*)d_in[6];
    const float* bv   = (const float*)d_in[7];
    const float* Wo   = (const float*)d_in[8];
    const float* bo   = (const float*)d_in[9];
    const float* W1   = (const float*)d_in[10];
    const float* b1   = (const float*)d_in[11];
    const float* W2   = (const float*)d_in[12];
    const float* b2   = (const float*)d_in[13];
    const float* W3   = (const float*)d_in[14];
    const float* b3   = (const float*)d_in[15];
    const float* ln1g = (const float*)d_in[16];
    const float* ln1b = (const float*)d_in[17];
    const float* ln2g = (const float*)d_in[18];
    const float* ln2b = (const float*)d_in[19];
    const float* rc   = (const float*)d_in[20];
    const float* rs   = (const float*)d_in[21];
    float* out = (float*)d_out;

    float *x2, *qh, *kh, *vh, *attn, *res, *h1, *wqkv, *bqkv, *wr;
    cudaGetSymbolAddress((void**)&x2,   g_x2);
    cudaGetSymbolAddress((void**)&qh,   g_qh);
    cudaGetSymbolAddress((void**)&kh,   g_kh);
    cudaGetSymbolAddress((void**)&vh,   g_vh);
    cudaGetSymbolAddress((void**)&attn, g_attn);
    cudaGetSymbolAddress((void**)&res,  g_res);
    cudaGetSymbolAddress((void**)&h1,   g_h1);
    cudaGetSymbolAddress((void**)&wqkv, g_wqkv);
    cudaGetSymbolAddress((void**)&bqkv, g_bqkv);
    cudaGetSymbolAddress((void**)&wr,   g_wr);

    cudaFuncSetAttribute(gemm_tc<EPI_BIAS>,     cudaFuncAttributeMaxDynamicSharedMemorySize, SMEM_BYTES);
    cudaFuncSetAttribute(gemm_tc<EPI_BIAS_RES>, cudaFuncAttributeMaxDynamicSharedMemorySize, SMEM_BYTES);
    cudaFuncSetAttribute(gemm_tc<EPI_SWIGLU>,   cudaFuncAttributeMaxDynamicSharedMemorySize, SMEM_BYTES);
    cudaFuncSetAttribute(flash_k,               cudaFuncAttributeMaxDynamicSharedMemorySize, FLASH_SMEM);

    const float iscale = 1.f / sqrtf((float)CDK);

    // 0) RN-round weights + pack QKV
    round4_k<<<(291600 + 255) / 256, 256>>>(Wo, wr + WR_WO, 291600);
    round4_k<<<(874800 + 255) / 256, 256>>>(W1, wr + WR_W1, 874800);
    round4_k<<<(874800 + 255) / 256, 256>>>(W3, wr + WR_W3, 874800);
    round4_k<<<(874800 + 255) / 256, 256>>>(W2, wr + WR_W2, 874800);
    {
        int total = CD * (CD / 4) + CD / 4;
        pack_qkv_k<<<(total + 255) / 256, 256>>>(Wq, Wk, Wv, bq, bk, bv, wqkv, bqkv);
    }

    // 1) LN1
    ln_k<<<CBS, 256>>>(x, ln1g, ln1b, x2);

    // 2) fused QKV projection
    dim3 gQKV((CFF + 127) / 128, (CBS + 127) / 128, 1);
    gemm_tc<EPI_BIAS><<<gQKV, 256, SMEM_BYTES>>>(
        x2, CD, wqkv, CFF, h1, CFF, bqkv, nullptr, 0, CBS, CFF, CD);

    // 3) RoPE + repack
    {
        long total = (long)CB * CH * CS * 48;
        rope_repack_k<<<(unsigned)((total + 255) / 256), 256>>>(h1, rc, rs, qh, kh, vh);
    }

    // 4) flash attention (register-resident, split K/V wait)
    {
        dim3 g((CS + FQ - 1) / FQ, CB * CH);
        flash_k<<<g, 256, FLASH_SMEM>>>(qh, kh, vh, attn, iscale);
    }

    // 5) O-projection + bias + residual(x)
    dim3 gD((CD + 127) / 128, (CBS + 127) / 128, 1);
    gemm_tc<EPI_BIAS_RES><<<gD, 256, SMEM_BYTES>>>(
        attn, CD, wr + WR_WO, CD, res, CD, bo, x, CD, CBS, CD, CD);

    // 6) LN2
    ln_k<<<CBS, 256>>>(res, ln2g, ln2b, x2);

    // 7) h1 = x2@W1 + b1
    dim3 gF((CFF + 127) / 128, (CBS + 127) / 128, 1);
    gemm_tc<EPI_BIAS><<<gF, 256, SMEM_BYTES>>>(
        x2, CD, wr + WR_W1, CFF, h1, CFF, b1, nullptr, 0, CBS, CFF, CD);

    // 8) h1 = silu(h1) * (x2@W3 + b3)
    gemm_tc<EPI_SWIGLU><<<gF, 256, SMEM_BYTES>>>(
        x2, CD, wr + WR_W3, CFF, h1, CFF, b3, h1, CFF, CBS, CFF, CD);

    // 9) out = res + h1@W2 + b2
    gemm_tc<EPI_BIAS_RES><<<gD, 256, SMEM_BYTES>>>(
        h1, CFF, wr + WR_W2, CD, out, CD, b2, res, CD, CBS, CD, CFF);
}

// round 12
// speedup vs baseline: 3.0619x; 2.9944x over previous
#include <cuda_runtime.h>
#include <cuda_fp16.h>
#include <mma.h>
#include <math.h>

using namespace nvcuda;

// Problem dims
#define CB  8
#define CS  1300
#define CD  1080
#define CH  12
#define CDK 90
#define CDP 96
#define CFF 3240
#define CBS (CB*CS)

// ---------------- scratch ----------------
__device__ half  g_x2h [(size_t)CBS*CD];       // LN output (fp16)
__device__ half  g_qkvh[(size_t)CBS*CFF];      // fused QKV output (fp16)
__device__ half  g_h1h [(size_t)CBS*CFF];      // FFN intermediate (fp16)
__device__ half  g_attnh[(size_t)CBS*CD];      // flash output (fp16)
__device__ float g_qh [(size_t)CB*CH*CS*CDP];
__device__ float g_kh [(size_t)CB*CH*CS*CDP];
__device__ float g_vh [(size_t)CB*CH*CS*CDP];
__device__ float g_res[(size_t)CBS*CD];        // residual stream (f32)
__device__ half  g_wqkvh[(size_t)CD*CFF];      // packed Wq|Wk|Wv (fp16)
__device__ float g_bqkv[CFF];
__device__ half  g_wrh [(size_t)11664000];     // fp16 Wo|W1|W3|W2
#define WR_WO 0
#define WR_W1 1166400
#define WR_W3 4665600
#define WR_W2 8164800

enum { EPI_NONE=0, EPI_SCALE=1, EPI_BIAS=2, EPI_BIAS_RES=3, EPI_SWIGLU=4 };

__device__ __forceinline__ float rn_tf32(float x)
{
    float r;
    asm("cvt.rna.tf32.f32 %0, %1;" : "=f"(r) : "f"(x));
    return r;
}

__device__ __forceinline__ void cp_async16(void* smem, const void* gmem, bool pred)
{
    unsigned saddr = (unsigned)__cvta_generic_to_shared(smem);
    int sz = pred ? 16 : 0;
    asm volatile("cp.async.cg.shared.global [%0], [%1], 16, %2;\n"
                 :: "r"(saddr), "l"(gmem), "r"(sz));
}
__device__ __forceinline__ void cp_commit() { asm volatile("cp.async.commit_group;\n"); }

// raw tf32 mma m16n8k8 (flash only)
__device__ __forceinline__ void mma_tf32(float* d,
    unsigned a0, unsigned a1, unsigned a2, unsigned a3,
    unsigned b0, unsigned b1)
{
    asm volatile("mma.sync.aligned.m16n8k8.row.col.f32.tf32.tf32.f32 "
                 "{%0,%1,%2,%3}, {%4,%5,%6,%7}, {%8,%9}, {%0,%1,%2,%3};"
                 : "+f"(d[0]), "+f"(d[1]), "+f"(d[2]), "+f"(d[3])
                 : "r"(a0), "r"(a1), "r"(a2), "r"(a3), "r"(b0), "r"(b1));
}

// epilogue store/load helpers (f32 vs fp16 paths)
__device__ __forceinline__ void store4(float* p, float4 v)
{
    *reinterpret_cast<float4*>(p) = v;
}
__device__ __forceinline__ void store4(half* p, float4 v)
{
    half2* h = reinterpret_cast<half2*>(p);
    h[0] = __floats2half2_rn(v.x, v.y);
    h[1] = __floats2half2_rn(v.z, v.w);
}
__device__ __forceinline__ float4 load4aux(const float* p)
{
    return *reinterpret_cast<const float4*>(p);
}
__device__ __forceinline__ float4 load4aux(const half* p)
{
    const half2* h = reinterpret_cast<const half2*>(p);
    float2 a = __half22float2(h[0]);
    float2 b = __half22float2(h[1]);
    return make_float4(a.x, a.y, b.x, b.y);
}

// ------ FP16 GEMM: 128x128 tile, 32x64 warp tile, BK=32, 4-stage, 2 CTA/SM --
#define ALDH 40                     // halfs per A row (32 + 8 pad)
#define BLDH 136                    // halfs per B row [k][n] (128 + 8 pad)
#define CLD 24
#define STG_A_H (128*ALDH)          // 5120 halfs
#define STG_B_H (32*BLDH)           // 4352 halfs
#define STG_H (STG_A_H+STG_B_H)     // 9472 halfs / stage
#define SMEM_BYTES (4*STG_H*2)      // 75776 B

template<int EPI, typename OutT, typename AuxT>
__global__ __launch_bounds__(256, 2)
void gemm_h(const half* __restrict__ A, int lda,
            const half* __restrict__ Bm, int ldb,
            OutT* __restrict__ C, int ldc,
            const float* __restrict__ bias,
            const AuxT* __restrict__ aux, int ldx,
            int M, int N, int K)
{
    const int m0 = blockIdx.y * 128;
    const int n0 = blockIdx.x * 128;
    const int kEnd  = K;
    const int nIter = (kEnd + 31) >> 5;

    extern __shared__ __align__(16) char smem_raw[];
    half* smem_h = reinterpret_cast<half*>(smem_raw);

    const int tid = threadIdx.x;
    const int wid = tid >> 5;
    const int lane = tid & 31;
    const int warp_m = wid & 3;
    const int warp_n = wid >> 2;

    const int aRow = tid >> 1;          // 0..127
    const int aC0  = (tid & 1) * 16;    // 0 or 16 (halfs)
    const int bRow = tid >> 3;          // 0..31
    const int bC0  = (tid & 7) * 16;    // 0..112 (halfs)

    const bool aRowOk = (m0 + aRow) < M;
    const half* aBase = A + (long)(m0 + aRow) * lda + aC0;
    const half* bBase = Bm + (long)bRow * ldb + n0 + bC0;
    const bool bColOk  = (n0 + bC0) < N;        // N % 8 == 0: chunk all-in/out
    const bool bColOk8 = (n0 + bC0 + 8) < N;

    wmma::fragment<wmma::accumulator, 16, 16, 16, float> acc[2][4];
    #pragma unroll
    for (int i = 0; i < 2; i++)
        #pragma unroll
        for (int j = 0; j < 4; j++) wmma::fill_fragment(acc[i][j], 0.f);

    auto issue = [&](int it, int buf) {
        const int k0 = it << 5;
        half* as = smem_h + buf * STG_H;
        half* bs = as + STG_A_H;
        // A: K % 8 == 0 so an 8-half chunk is in iff its start < kEnd
        cp_async16(&as[aRow * ALDH + aC0],     aBase + k0,     aRowOk && (k0 + aC0     < kEnd));
        cp_async16(&as[aRow * ALDH + aC0 + 8], aBase + k0 + 8, aRowOk && (k0 + aC0 + 8 < kEnd));
        const bool rOk = (k0 + bRow) < kEnd;
        cp_async16(&bs[bRow * BLDH + bC0],     bBase + (long)k0 * ldb,     rOk && bColOk);
        cp_async16(&bs[bRow * BLDH + bC0 + 8], bBase + (long)k0 * ldb + 8, rOk && bColOk8);
    };

    issue(0, 0); cp_commit();
    if (nIter > 1) { issue(1, 1); cp_commit(); }
    if (nIter > 2) { issue(2, 2); cp_commit(); }

    for (int it = 0; it < nIter; it++) {
        const int buf = it & 3;
        if (it + 2 < nIter)      asm volatile("cp.async.wait_group 2;\n");
        else if (it + 1 < nIter) asm volatile("cp.async.wait_group 1;\n");
        else                     asm volatile("cp.async.wait_group 0;\n");
        __syncthreads();
        if (it + 3 < nIter) { issue(it + 3, (it + 3) & 3); cp_commit(); }

        const half* as = smem_h + buf * STG_H;
        const half* bs = as + STG_A_H;
        #pragma unroll
        for (int kk = 0; kk < 32; kk += 16) {
            wmma::fragment<wmma::matrix_a, 16, 16, 16, half, wmma::row_major> af[2];
            #pragma unroll
            for (int i = 0; i < 2; i++)
                wmma::load_matrix_sync(af[i], &as[(warp_m * 32 + i * 16) * ALDH + kk], ALDH);
            #pragma unroll
            for (int j = 0; j < 4; j++) {
                wmma::fragment<wmma::matrix_b, 16, 16, 16, half, wmma::row_major> bf;
                wmma::load_matrix_sync(bf, &bs[kk * BLDH + warp_n * 64 + j * 16], BLDH);
                wmma::mma_sync(acc[0][j], af[0], bf, acc[0][j]);
                wmma::mma_sync(acc[1][j], af[1], bf, acc[1][j]);
            }
        }
        // no bottom sync (4-stage: next issue hits buffer fenced at top)
    }
    __syncthreads();   // protect smem reuse by epilogue stage

    float* fstage = reinterpret_cast<float*>(smem_raw) + wid * 16 * CLD;
    const int er  = lane >> 1;
    const int ec0 = (lane & 1) * 8;
    #pragma unroll
    for (int i = 0; i < 2; i++) {
        #pragma unroll
        for (int j = 0; j < 4; j++) {
            wmma::store_matrix_sync(fstage, acc[i][j], CLD, wmma::mem_row_major);
            __syncwarp();
            const int gr = m0 + warp_m * 32 + i * 16 + er;
            const int gcb = n0 + warp_n * 64 + j * 16 + ec0;
            if (gr < M) {
                #pragma unroll
                for (int h4 = 0; h4 < 2; h4++) {
                    const int gc = gcb + h4 * 4;
                    if (gc + 3 < N) {
                        float4 v = *reinterpret_cast<const float4*>(&fstage[er * CLD + ec0 + h4 * 4]);
                        if (EPI == EPI_BIAS) {
                            float4 bv = *reinterpret_cast<const float4*>(&bias[gc]);
                            v.x += bv.x; v.y += bv.y; v.z += bv.z; v.w += bv.w;
                        }
                        if (EPI == EPI_BIAS_RES) {
                            float4 bv = *reinterpret_cast<const float4*>(&bias[gc]);
                            float4 av = load4aux(&aux[(long)gr * ldx + gc]);
                            v.x += bv.x + av.x; v.y += bv.y + av.y;
                            v.z += bv.z + av.z; v.w += bv.w + av.w;
                        }
                        if (EPI == EPI_SWIGLU) {
                            float4 bv = *reinterpret_cast<const float4*>(&bias[gc]);
                            float4 hv = load4aux(&aux[(long)gr * ldx + gc]);
                            v.x = (hv.x / (1.f + __expf(-hv.x))) * (v.x + bv.x);
                            v.y = (hv.y / (1.f + __expf(-hv.y))) * (v.y + bv.y);
                            v.z = (hv.z / (1.f + __expf(-hv.z))) * (v.z + bv.z);
                            v.w = (hv.w / (1.f + __expf(-hv.w))) * (v.w + bv.w);
                        }
                        store4(&C[(long)gr * ldc + gc], v);
                    }
                }
            }
            __syncwarp();
        }
    }
}

// --------- flash attention (tf32, register S/P/O) — output fp16 ------------
#define FQ 128
#define FN 64
#define QLD 100
#define FLASH_SMEM ((FQ*QLD + 2*FN*QLD)*4)   // 102400 B

__global__ __launch_bounds__(256, 2)
void flash_k(const float* __restrict__ qh, const float* __restrict__ kh,
             const float* __restrict__ vh, half* __restrict__ attn, float iscale)
{
    const int zi = blockIdx.y;
    const int iT = (int)gridDim.x - 1 - (int)blockIdx.x;  // heavy tiles first
    const int i0 = iT * FQ;
    const int tid = threadIdx.x;
    const int wid = tid >> 5;
    const int lane = tid & 31;
    const int g = lane >> 2;
    const int t = lane & 3;

    const float* Qp = qh + (long)zi * CS * CDP;
    const float* Kp = kh + (long)zi * CS * CDP;
    const float* Vp = vh + (long)zi * CS * CDP;

    extern __shared__ __align__(16) float sm[];
    float* Qs = sm;                  // [128][100]
    float* Ks = sm + FQ * QLD;       // [64][100]
    float* Vs = Ks + FN * QLD;       // [64][100]

    for (int tt = tid; tt < FQ * 24; tt += 256) {
        int r = tt / 24, c4 = (tt % 24) * 4;
        cp_async16(&Qs[r * QLD + c4], Qp + (long)(i0 + r) * CDP + c4, (i0 + r) < CS);
    }
    cp_commit();

    float oacc[12][4];
    #pragma unroll
    for (int n = 0; n < 12; n++)
        #pragma unroll
        for (int s = 0; s < 4; s++) oacc[n][s] = 0.f;
    float m0 = -1e30f, m1 = -1e30f, l0 = 0.f, l1 = 0.f;

    const int rw = wid * 16;
    const int row0 = i0 + rw + g;
    const int row1 = row0 + 8;
    const int jn = (min(CS, i0 + FQ) + FN - 1) / FN;

    asm volatile("cp.async.wait_group 0;\n");
    __syncthreads();

    for (int j = 0; j < jn; j++) {
        const int j0 = j * FN;
        __syncthreads();
        for (int tt = tid; tt < FN * 24; tt += 256) {
            int r = tt / 24, c4 = (tt % 24) * 4;
            cp_async16(&Ks[r * QLD + c4], Kp + (long)(j0 + r) * CDP + c4, (j0 + r) < CS);
        }
        cp_commit();
        for (int tt = tid; tt < FN * 24; tt += 256) {
            int r = tt / 24, c4 = (tt % 24) * 4;
            cp_async16(&Vs[r * QLD + c4], Vp + (long)(j0 + r) * CDP + c4, (j0 + r) < CS);
        }
        cp_commit();
        asm volatile("cp.async.wait_group 1;\n");
        __syncthreads();

        const bool active = (j0 <= i0 + rw + 15);
        float sacc[8][4];

        if (active) {
            #pragma unroll
            for (int n = 0; n < 8; n++)
                #pragma unroll
                for (int s = 0; s < 4; s++) sacc[n][s] = 0.f;

            #pragma unroll
            for (int kf = 0; kf < 12; kf++) {
                const int kc = kf * 8;
                unsigned a0 = __float_as_uint(Qs[(rw + g)     * QLD + kc + t]);
                unsigned a1 = __float_as_uint(Qs[(rw + g + 8) * QLD + kc + t]);
                unsigned a2 = __float_as_uint(Qs[(rw + g)     * QLD + kc + t + 4]);
                unsigned a3 = __float_as_uint(Qs[(rw + g + 8) * QLD + kc + t + 4]);
                #pragma unroll
                for (int nf = 0; nf < 8; nf++) {
                    unsigned b0 = __float_as_uint(Ks[(nf * 8 + g) * QLD + kc + t]);
                    unsigned b1 = __float_as_uint(Ks[(nf * 8 + g) * QLD + kc + t + 4]);
                    mma_tf32(sacc[nf], a0, a1, a2, a3, b0, b1);
                }
            }

            float rmax0 = -1e30f, rmax1 = -1e30f;
            #pragma unroll
            for (int nf = 0; nf < 8; nf++) {
                const int c0 = j0 + nf * 8 + 2 * t;
                float s0 = sacc[nf][0] * iscale; if (c0     > row0) s0 = -1e30f;
                float s1 = sacc[nf][1] * iscale; if (c0 + 1 > row0) s1 = -1e30f;
                float s2 = sacc[nf][2] * iscale; if (c0     > row1) s2 = -1e30f;
                float s3 = sacc[nf][3] * iscale; if (c0 + 1 > row1) s3 = -1e30f;
                sacc[nf][0] = s0; sacc[nf][1] = s1; sacc[nf][2] = s2; sacc[nf][3] = s3;
                rmax0 = fmaxf(rmax0, fmaxf(s0, s1));
                rmax1 = fmaxf(rmax1, fmaxf(s2, s3));
            }
            rmax0 = fmaxf(rmax0, __shfl_xor_sync(0xffffffffu, rmax0, 1));
            rmax0 = fmaxf(rmax0, __shfl_xor_sync(0xffffffffu, rmax0, 2));
            rmax1 = fmaxf(rmax1, __shfl_xor_sync(0xffffffffu, rmax1, 1));
            rmax1 = fmaxf(rmax1, __shfl_xor_sync(0xffffffffu, rmax1, 2));

            const float mn0 = fmaxf(m0, rmax0);
            const float mn1 = fmaxf(m1, rmax1);
            const float al0 = __expf(m0 - mn0);
            const float al1 = __expf(m1 - mn1);
            float ps0 = 0.f, ps1 = 0.f;
            #pragma unroll
            for (int nf = 0; nf < 8; nf++) {
                float p0 = rn_tf32(__expf(sacc[nf][0] - mn0));
                float p1 = rn_tf32(__expf(sacc[nf][1] - mn0));
                float p2 = rn_tf32(__expf(sacc[nf][2] - mn1));
                float p3 = rn_tf32(__expf(sacc[nf][3] - mn1));
                sacc[nf][0] = p0; sacc[nf][1] = p1; sacc[nf][2] = p2; sacc[nf][3] = p3;
                ps0 += p0 + p1; ps1 += p2 + p3;
            }
            ps0 += __shfl_xor_sync(0xffffffffu, ps0, 1);
            ps0 += __shfl_xor_sync(0xffffffffu, ps0, 2);
            ps1 += __shfl_xor_sync(0xffffffffu, ps1, 1);
            ps1 += __shfl_xor_sync(0xffffffffu, ps1, 2);
            l0 = l0 * al0 + ps0;  m0 = mn0;
            l1 = l1 * al1 + ps1;  m1 = mn1;

            #pragma unroll
            for (int n = 0; n < 12; n++) {
                oacc[n][0] *= al0; oacc[n][1] *= al0;
                oacc[n][2] *= al1; oacc[n][3] *= al1;
            }
        }

        asm volatile("cp.async.wait_group 0;\n");
        __syncthreads();

        if (active) {
            const int srcA = (lane & ~3) | (t >> 1);
            const int srcB = srcA + 2;
            #pragma unroll
            for (int kf = 0; kf < 8; kf++) {
                float v00 = __shfl_sync(0xffffffffu, sacc[kf][0], srcA);
                float v01 = __shfl_sync(0xffffffffu, sacc[kf][1], srcA);
                float v20 = __shfl_sync(0xffffffffu, sacc[kf][2], srcA);
                float v21 = __shfl_sync(0xffffffffu, sacc[kf][3], srcA);
                float w00 = __shfl_sync(0xffffffffu, sacc[kf][0], srcB);
                float w01 = __shfl_sync(0xffffffffu, sacc[kf][1], srcB);
                float w20 = __shfl_sync(0xffffffffu, sacc[kf][2], srcB);
                float w21 = __shfl_sync(0xffffffffu, sacc[kf][3], srcB);
                unsigned a0 = __float_as_uint((t & 1) ? v01 : v00);
                unsigned a1 = __float_as_uint((t & 1) ? v21 : v20);
                unsigned a2 = __float_as_uint((t & 1) ? w01 : w00);
                unsigned a3 = __float_as_uint((t & 1) ? w21 : w20);
                #pragma unroll
                for (int nf = 0; nf < 12; nf++) {
                    unsigned b0 = __float_as_uint(Vs[(kf * 8 + t)     * QLD + nf * 8 + g]);
                    unsigned b1 = __float_as_uint(Vs[(kf * 8 + t + 4) * QLD + nf * 8 + g]);
                    mma_tf32(oacc[nf], a0, a1, a2, a3, b0, b1);
                }
            }
        }
    }

    const int b = zi / CH, h = zi - b * CH;
    const float il0 = (l0 > 0.f) ? 1.f / l0 : 0.f;
    const float il1 = (l1 > 0.f) ? 1.f / l1 : 0.f;
    #pragma unroll
    for (int nf = 0; nf < 12; nf++) {
        const int c0 = nf * 8 + 2 * t;
        if (c0 < CDK) {
            if (row0 < CS) {
                half2 v = __floats2half2_rn(oacc[nf][0] * il0, oacc[nf][1] * il0);
                *reinterpret_cast<half2*>(&attn[((long)b * CS + row0) * CD + h * CDK + c0]) = v;
            }
            if (row1 < CS) {
                half2 v = __floats2half2_rn(oacc[nf][2] * il1, oacc[nf][3] * il1);
                *reinterpret_cast<half2*>(&attn[((long)b * CS + row1) * CD + h * CDK + c0]) = v;
            }
        }
    }
}

// ---------------- f32 -> fp16 convert copy ----------------
__global__ __launch_bounds__(256)
void cvt_half_k(const float* __restrict__ s, half* __restrict__ d, int n4)
{
    int i = blockIdx.x * 256 + threadIdx.x;
    if (i < n4) {
        float4 v = reinterpret_cast<const float4*>(s)[i];
        half2* p = reinterpret_cast<half2*>(d + (size_t)i * 4);
        p[0] = __floats2half2_rn(v.x, v.y);
        p[1] = __floats2half2_rn(v.z, v.w);
    }
}

// ---------------- pack Wq|Wk|Wv -> fp16 [1080][3240] ----------------
__global__ __launch_bounds__(256)
void pack_qkv_k(const float* __restrict__ Wq, const float* __restrict__ Wk,
                const float* __restrict__ Wv,
                const float* __restrict__ bq, const float* __restrict__ bk,
                const float* __restrict__ bv,
                half* __restrict__ W, float* __restrict__ b)
{
    const int NW4 = CD * (CD / 4);
    long idx = (long)blockIdx.x * 256 + threadIdx.x;
    if (idx < NW4) {
        int r = (int)(idx / (CD / 4));
        int c = (int)(idx % (CD / 4)) * 4;
        float4 vq = *reinterpret_cast<const float4*>(Wq + (long)r * CD + c);
        float4 vk = *reinterpret_cast<const float4*>(Wk + (long)r * CD + c);
        float4 vv = *reinterpret_cast<const float4*>(Wv + (long)r * CD + c);
        half2* pq = reinterpret_cast<half2*>(W + (long)r * CFF + c);
        half2* pk = reinterpret_cast<half2*>(W + (long)r * CFF + CD + c);
        half2* pv = reinterpret_cast<half2*>(W + (long)r * CFF + 2 * CD + c);
        pq[0] = __floats2half2_rn(vq.x, vq.y); pq[1] = __floats2half2_rn(vq.z, vq.w);
        pk[0] = __floats2half2_rn(vk.x, vk.y); pk[1] = __floats2half2_rn(vk.z, vk.w);
        pv[0] = __floats2half2_rn(vv.x, vv.y); pv[1] = __floats2half2_rn(vv.z, vv.w);
    } else if (idx < NW4 + CD / 4) {
        int c = (int)(idx - NW4) * 4;
        *reinterpret_cast<float4*>(b + c)          = *reinterpret_cast<const float4*>(bq + c);
        *reinterpret_cast<float4*>(b + CD + c)     = *reinterpret_cast<const float4*>(bk + c);
        *reinterpret_cast<float4*>(b + 2 * CD + c) = *reinterpret_cast<const float4*>(bv + c);
    }
}

// ---------------- layernorm -> fp16 output ----------------
__global__ __launch_bounds__(256)
void ln_k(const float* __restrict__ x, const float* __restrict__ g,
          const float* __restrict__ b, half* __restrict__ y)
{
    const long row = blockIdx.x;
    const float* xr = x + row * CD;
    half* yr = y + row * CD;

    float s = 0.f, s2 = 0.f;
    for (int i = threadIdx.x; i < CD; i += 256) {
        float v = xr[i]; s += v; s2 += v * v;
    }
    __shared__ float rs[8], rs2[8];
    __shared__ float bm, br;
    #pragma unroll
    for (int o = 16; o; o >>= 1) {
        s  += __shfl_xor_sync(0xffffffffu, s,  o);
        s2 += __shfl_xor_sync(0xffffffffu, s2, o);
    }
    if ((threadIdx.x & 31) == 0) { rs[threadIdx.x >> 5] = s; rs2[threadIdx.x >> 5] = s2; }
    __syncthreads();
    if (threadIdx.x < 8) {
        float a = rs[threadIdx.x], a2 = rs2[threadIdx.x];
        #pragma unroll
        for (int o = 4; o; o >>= 1) {
            a  += __shfl_xor_sync(0xffu, a,  o);
            a2 += __shfl_xor_sync(0xffu, a2, o);
        }
        if (threadIdx.x == 0) {
            float mean = a / CD;
            float var  = a2 / CD - mean * mean;
            bm = mean;
            br = rsqrtf(var + 1e-5f);
        }
    }
    __syncthreads();
    const float mean = bm, rstd = br;
    for (int i = threadIdx.x; i < CD; i += 256)
        yr[i] = __float2half((xr[i] - mean) * rstd * g[i] + b[i]);
}

// -------- RoPE + repack from fp16 fused QKV to f32 [B*H, S, 96] (tf32 RN) ---
__global__ __launch_bounds__(256)
void rope_repack_k(const half* __restrict__ qkv,
                   const float* __restrict__ ct, const float* __restrict__ st,
                   float* __restrict__ qh, float* __restrict__ kh,
                   float* __restrict__ vh)
{
    const long total = (long)CB * CH * CS * 48;
    long idx = (long)blockIdx.x * 256 + threadIdx.x;
    if (idx >= total) return;
    const int d = (int)(idx % 48);  idx /= 48;
    const int s = (int)(idx % CS);  idx /= CS;
    const int h = (int)(idx % CH);
    const int b = (int)(idx / CH);

    const long src = ((long)b * CS + s) * CFF + h * CDK;
    const long dst = (((long)b * CH + h) * CS + s) * CDP;

    if (d < 45) {
        const float c1 = ct[s * CDK + d],      s1 = st[s * CDK + d];
        const float c2 = ct[s * CDK + d + 45], s2 = st[s * CDK + d + 45];
        float q1 = __half2float(qkv[src + d]),      q2 = __half2float(qkv[src + d + 45]);
        qh[dst + d]      = rn_tf32(q1 * c1 - q2 * s1);
        qh[dst + d + 45] = rn_tf32(q2 * c2 + q1 * s2);
        float k1 = __half2float(qkv[src + CD + d]), k2 = __half2float(qkv[src + CD + d + 45]);
        kh[dst + d]      = rn_tf32(k1 * c1 - k2 * s1);
        kh[dst + d + 45] = rn_tf32(k2 * c2 + k1 * s2);
        vh[dst + d]      = rn_tf32(__half2float(qkv[src + 2 * CD + d]));
        vh[dst + d + 45] = rn_tf32(__half2float(qkv[src + 2 * CD + d + 45]));
    } else {
        const int p = 90 + 2 * (d - 45);
        qh[dst + p] = 0.f; qh[dst + p + 1] = 0.f;
        kh[dst + p] = 0.f; kh[dst + p + 1] = 0.f;
        vh[dst + p] = 0.f; vh[dst + p + 1] = 0.f;
    }
}

// ---------------- host launch ----------------
extern "C" void kernel_launch(void* const* d_in, const int* in_sizes, int n_in,
                              void* d_out, int out_size)
{
    const float* x    = (const float*)d_in[0];
    const float* Wq   = (const float*)d_in[2];
    const float* bq   = (const float*)d_in[3];
    const float* Wk   = (const float*)d_in[4];
    const float* bk   = (const float*)d_in[5];
    const float* Wv   = (const float*)d_in[6];
    const float* bv   = (const float*)d_in[7];
    const float* Wo   = (const float*)d_in[8];
    const float* bo   = (const float*)d_in[9];
    const float* W1   = (const float*)d_in[10];
    const float* b1   = (const float*)d_in[11];
    const float* W2   = (const float*)d_in[12];
    const float* b2   = (const float*)d_in[13];
    const float* W3   = (const float*)d_in[14];
    const float* b3   = (const float*)d_in[15];
    const float* ln1g = (const float*)d_in[16];
    const float* ln1b = (const float*)d_in[17];
    const float* ln2g = (const float*)d_in[18];
    const float* ln2b = (const float*)d_in[19];
    const float* rc   = (const float*)d_in[20];
    const float* rs   = (const float*)d_in[21];
    float* out = (float*)d_out;

    half *x2h, *qkvh, *h1h, *attnh, *wqkvh, *wrh;
    float *qh, *kh, *vh, *res, *bqkv;
    cudaGetSymbolAddress((void**)&x2h,   g_x2h);
    cudaGetSymbolAddress((void**)&qkvh,  g_qkvh);
    cudaGetSymbolAddress((void**)&h1h,   g_h1h);
    cudaGetSymbolAddress((void**)&attnh, g_attnh);
    cudaGetSymbolAddress((void**)&qh,    g_qh);
    cudaGetSymbolAddress((void**)&kh,    g_kh);
    cudaGetSymbolAddress((void**)&vh,    g_vh);
    cudaGetSymbolAddress((void**)&res,   g_res);
    cudaGetSymbolAddress((void**)&wqkvh, g_wqkvh);
    cudaGetSymbolAddress((void**)&bqkv,  g_bqkv);
    cudaGetSymbolAddress((void**)&wrh,   g_wrh);

    cudaFuncSetAttribute((const void*)gemm_h<EPI_BIAS, half, float>,
                         cudaFuncAttributeMaxDynamicSharedMemorySize, SMEM_BYTES);
    cudaFuncSetAttribute((const void*)gemm_h<EPI_BIAS_RES, float, float>,
                         cudaFuncAttributeMaxDynamicSharedMemorySize, SMEM_BYTES);
    cudaFuncSetAttribute((const void*)gemm_h<EPI_SWIGLU, half, half>,
                         cudaFuncAttributeMaxDynamicSharedMemorySize, SMEM_BYTES);
    cudaFuncSetAttribute((const void*)flash_k,
                         cudaFuncAttributeMaxDynamicSharedMemorySize, FLASH_SMEM);

    const float iscale = 1.f / sqrtf((float)CDK);

    // 0) fp16 weights + pack QKV
    cvt_half_k<<<(291600 + 255) / 256, 256>>>(Wo, wrh + WR_WO, 291600);
    cvt_half_k<<<(874800 + 255) / 256, 256>>>(W1, wrh + WR_W1, 874800);
    cvt_half_k<<<(874800 + 255) / 256, 256>>>(W3, wrh + WR_W3, 874800);
    cvt_half_k<<<(874800 + 255) / 256, 256>>>(W2, wrh + WR_W2, 874800);
    {
        int total = CD * (CD / 4) + CD / 4;
        pack_qkv_k<<<(total + 255) / 256, 256>>>(Wq, Wk, Wv, bq, bk, bv, wqkvh, bqkv);
    }

    // 1) LN1 -> fp16
    ln_k<<<CBS, 256>>>(x, ln1g, ln1b, x2h);

    // 2) fused QKV projection (fp16 in, fp16 out)
    dim3 gQKV((CFF + 127) / 128, (CBS + 127) / 128, 1);
    gemm_h<EPI_BIAS, half, float><<<gQKV, 256, SMEM_BYTES>>>(
        x2h, CD, wqkvh, CFF, qkvh, CFF, bqkv, (const float*)nullptr, 0, CBS, CFF, CD);

    // 3) RoPE + repack (fp16 -> tf32-RN f32)
    {
        long total = (long)CB * CH * CS * 48;
        rope_repack_k<<<(unsigned)((total + 255) / 256), 256>>>(qkvh, rc, rs, qh, kh, vh);
    }

    // 4) flash attention (tf32), output fp16
    {
        dim3 g((CS + FQ - 1) / FQ, CB * CH);
        flash_k<<<g, 256, FLASH_SMEM>>>(qh, kh, vh, attnh, iscale);
    }

    // 5) O-projection + bias + residual(x) -> f32 res
    dim3 gD((CD + 127) / 128, (CBS + 127) / 128, 1);
    gemm_h<EPI_BIAS_RES, float, float><<<gD, 256, SMEM_BYTES>>>(
        attnh, CD, wrh + WR_WO, CD, res, CD, bo, x, CD, CBS, CD, CD);

    // 6) LN2 -> fp16
    ln_k<<<CBS, 256>>>(res, ln2g, ln2b, x2h);

    // 7) h1 = x2@W1 + b1  (fp16 out)
    dim3 gF((CFF + 127) / 128, (CBS + 127) / 128, 1);
    gemm_h<EPI_BIAS, half, float><<<gF, 256, SMEM_BYTES>>>(
        x2h, CD, wrh + WR_W1, CFF, h1h, CFF, b1, (const float*)nullptr, 0, CBS, CFF, CD);

    // 8) h1 = silu(h1) * (x2@W3 + b3)  (in-place fp16)
    gemm_h<EPI_SWIGLU, half, half><<<gF, 256, SMEM_BYTES>>>(
        x2h, CD, wrh + WR_W3, CFF, h1h, CFF, b3, h1h, CFF, CBS, CFF, CD);

    // 9) out = res + h1@W2 + b2  (f32)
    gemm_h<EPI_BIAS_RES, float, float><<<gD, 256, SMEM_BYTES>>>(
        h1h, CFF, wrh + WR_W2, CD, out, CD, b2, res, CD, CBS, CD, CFF);
}

// round 13
// speedup vs baseline: 3.3744x; 1.1020x over previous
#include <cuda_runtime.h>
#include <cuda_fp16.h>
#include <mma.h>
#include <math.h>

using namespace nvcuda;

// Problem dims
#define CB  8
#define CS  1300
#define CD  1080
#define CH  12
#define CDK 90
#define CDP 96
#define CFF 3240
#define CBS (CB*CS)

// ---------------- scratch ----------------
__device__ half  g_x2h [(size_t)CBS*CD];       // LN output (fp16)
__device__ half  g_qkvh[(size_t)CBS*CFF];      // fused QKV output (fp16)
__device__ half  g_h1h [(size_t)CBS*CFF];      // FFN intermediate (fp16)
__device__ half  g_attnh[(size_t)CBS*CD];      // flash output (fp16)
__device__ half  g_qhh[(size_t)CB*CH*CS*CDP];  // per-head roped Q (fp16)
__device__ half  g_khh[(size_t)CB*CH*CS*CDP];
__device__ half  g_vhh[(size_t)CB*CH*CS*CDP];
__device__ float g_res[(size_t)CBS*CD];        // residual stream (f32)
__device__ half  g_wqkvh[(size_t)CD*CFF];      // packed Wq|Wk|Wv (fp16)
__device__ float g_bqkv[CFF];
__device__ half  g_wrh [(size_t)11664000];     // fp16 Wo|W1|W3|W2
#define WR_WO 0
#define WR_W1 1166400
#define WR_W3 4665600
#define WR_W2 8164800

enum { EPI_NONE=0, EPI_SCALE=1, EPI_BIAS=2, EPI_BIAS_RES=3, EPI_SWIGLU=4 };

__device__ __forceinline__ void cp_async16(void* smem, const void* gmem, bool pred)
{
    unsigned saddr = (unsigned)__cvta_generic_to_shared(smem);
    int sz = pred ? 16 : 0;
    asm volatile("cp.async.cg.shared.global [%0], [%1], 16, %2;\n"
                 :: "r"(saddr), "l"(gmem), "r"(sz));
}
__device__ __forceinline__ void cp_commit() { asm volatile("cp.async.commit_group;\n"); }

// raw fp16 mma m16n8k16 (A row-major, B col-major, f32 accum, in-place)
__device__ __forceinline__ void mma_f16(float* d,
    unsigned a0, unsigned a1, unsigned a2, unsigned a3,
    unsigned b0, unsigned b1)
{
    asm volatile("mma.sync.aligned.m16n8k16.row.col.f32.f16.f16.f32 "
                 "{%0,%1,%2,%3}, {%4,%5,%6,%7}, {%8,%9}, {%0,%1,%2,%3};"
                 : "+f"(d[0]), "+f"(d[1]), "+f"(d[2]), "+f"(d[3])
                 : "r"(a0), "r"(a1), "r"(a2), "r"(a3), "r"(b0), "r"(b1));
}

// epilogue store/load helpers
__device__ __forceinline__ void store4(float* p, float4 v)
{
    *reinterpret_cast<float4*>(p) = v;
}
__device__ __forceinline__ void store4(half* p, float4 v)
{
    half2* h = reinterpret_cast<half2*>(p);
    h[0] = __floats2half2_rn(v.x, v.y);
    h[1] = __floats2half2_rn(v.z, v.w);
}
__device__ __forceinline__ float4 load4aux(const float* p)
{
    return *reinterpret_cast<const float4*>(p);
}
__device__ __forceinline__ float4 load4aux(const half* p)
{
    const half2* h = reinterpret_cast<const half2*>(p);
    float2 a = __half22float2(h[0]);
    float2 b = __half22float2(h[1]);
    return make_float4(a.x, a.y, b.x, b.y);
}

// ------ FP16 GEMM: 128x128 tile, 32x64 warp tile, BK=32, 4-stage, 2 CTA/SM --
#define ALDH 40
#define BLDH 136
#define CLD 24
#define STG_A_H (128*ALDH)
#define STG_B_H (32*BLDH)
#define STG_H (STG_A_H+STG_B_H)
#define SMEM_BYTES (4*STG_H*2)      // 75776 B

template<int EPI, typename OutT, typename AuxT>
__global__ __launch_bounds__(256, 2)
void gemm_h(const half* __restrict__ A, int lda,
            const half* __restrict__ Bm, int ldb,
            OutT* __restrict__ C, int ldc,
            const float* __restrict__ bias,
            const AuxT* __restrict__ aux, int ldx,
            int M, int N, int K)
{
    const int m0 = blockIdx.y * 128;
    const int n0 = blockIdx.x * 128;
    const int kEnd  = K;
    const int nIter = (kEnd + 31) >> 5;

    extern __shared__ __align__(16) char smem_raw[];
    half* smem_h = reinterpret_cast<half*>(smem_raw);

    const int tid = threadIdx.x;
    const int wid = tid >> 5;
    const int lane = tid & 31;
    const int warp_m = wid & 3;
    const int warp_n = wid >> 2;

    const int aRow = tid >> 1;
    const int aC0  = (tid & 1) * 16;
    const int bRow = tid >> 3;
    const int bC0  = (tid & 7) * 16;

    const bool aRowOk = (m0 + aRow) < M;
    const half* aBase = A + (long)(m0 + aRow) * lda + aC0;
    const half* bBase = Bm + (long)bRow * ldb + n0 + bC0;
    const bool bColOk  = (n0 + bC0) < N;
    const bool bColOk8 = (n0 + bC0 + 8) < N;

    wmma::fragment<wmma::accumulator, 16, 16, 16, float> acc[2][4];
    #pragma unroll
    for (int i = 0; i < 2; i++)
        #pragma unroll
        for (int j = 0; j < 4; j++) wmma::fill_fragment(acc[i][j], 0.f);

    auto issue = [&](int it, int buf) {
        const int k0 = it << 5;
        half* as = smem_h + buf * STG_H;
        half* bs = as + STG_A_H;
        cp_async16(&as[aRow * ALDH + aC0],     aBase + k0,     aRowOk && (k0 + aC0     < kEnd));
        cp_async16(&as[aRow * ALDH + aC0 + 8], aBase + k0 + 8, aRowOk && (k0 + aC0 + 8 < kEnd));
        const bool rOk = (k0 + bRow) < kEnd;
        cp_async16(&bs[bRow * BLDH + bC0],     bBase + (long)k0 * ldb,     rOk && bColOk);
        cp_async16(&bs[bRow * BLDH + bC0 + 8], bBase + (long)k0 * ldb + 8, rOk && bColOk8);
    };

    issue(0, 0); cp_commit();
    if (nIter > 1) { issue(1, 1); cp_commit(); }
    if (nIter > 2) { issue(2, 2); cp_commit(); }

    for (int it = 0; it < nIter; it++) {
        const int buf = it & 3;
        if (it + 2 < nIter)      asm volatile("cp.async.wait_group 2;\n");
        else if (it + 1 < nIter) asm volatile("cp.async.wait_group 1;\n");
        else                     asm volatile("cp.async.wait_group 0;\n");
        __syncthreads();
        if (it + 3 < nIter) { issue(it + 3, (it + 3) & 3); cp_commit(); }

        const half* as = smem_h + buf * STG_H;
        const half* bs = as + STG_A_H;
        #pragma unroll
        for (int kk = 0; kk < 32; kk += 16) {
            wmma::fragment<wmma::matrix_a, 16, 16, 16, half, wmma::row_major> af[2];
            #pragma unroll
            for (int i = 0; i < 2; i++)
                wmma::load_matrix_sync(af[i], &as[(warp_m * 32 + i * 16) * ALDH + kk], ALDH);
            #pragma unroll
            for (int j = 0; j < 4; j++) {
                wmma::fragment<wmma::matrix_b, 16, 16, 16, half, wmma::row_major> bf;
                wmma::load_matrix_sync(bf, &bs[kk * BLDH + warp_n * 64 + j * 16], BLDH);
                wmma::mma_sync(acc[0][j], af[0], bf, acc[0][j]);
                wmma::mma_sync(acc[1][j], af[1], bf, acc[1][j]);
            }
        }
    }
    __syncthreads();

    float* fstage = reinterpret_cast<float*>(smem_raw) + wid * 16 * CLD;
    const int er  = lane >> 1;
    const int ec0 = (lane & 1) * 8;
    #pragma unroll
    for (int i = 0; i < 2; i++) {
        #pragma unroll
        for (int j = 0; j < 4; j++) {
            wmma::store_matrix_sync(fstage, acc[i][j], CLD, wmma::mem_row_major);
            __syncwarp();
            const int gr = m0 + warp_m * 32 + i * 16 + er;
            const int gcb = n0 + warp_n * 64 + j * 16 + ec0;
            if (gr < M) {
                #pragma unroll
                for (int h4 = 0; h4 < 2; h4++) {
                    const int gc = gcb + h4 * 4;
                    if (gc + 3 < N) {
                        float4 v = *reinterpret_cast<const float4*>(&fstage[er * CLD + ec0 + h4 * 4]);
                        if (EPI == EPI_BIAS) {
                            float4 bv = *reinterpret_cast<const float4*>(&bias[gc]);
                            v.x += bv.x; v.y += bv.y; v.z += bv.z; v.w += bv.w;
                        }
                        if (EPI == EPI_BIAS_RES) {
                            float4 bv = *reinterpret_cast<const float4*>(&bias[gc]);
                            float4 av = load4aux(&aux[(long)gr * ldx + gc]);
                            v.x += bv.x + av.x; v.y += bv.y + av.y;
                            v.z += bv.z + av.z; v.w += bv.w + av.w;
                        }
                        if (EPI == EPI_SWIGLU) {
                            float4 bv = *reinterpret_cast<const float4*>(&bias[gc]);
                            float4 hv = load4aux(&aux[(long)gr * ldx + gc]);
                            v.x = (hv.x / (1.f + __expf(-hv.x))) * (v.x + bv.x);
                            v.y = (hv.y / (1.f + __expf(-hv.y))) * (v.y + bv.y);
                            v.z = (hv.z / (1.f + __expf(-hv.z))) * (v.z + bv.z);
                            v.w = (hv.w / (1.f + __expf(-hv.w))) * (v.w + bv.w);
                        }
                        store4(&C[(long)gr * ldc + gc], v);
                    }
                }
            }
            __syncwarp();
        }
    }
}

// ------------- flash attention: fp16 m16n8k16, register S/P/O --------------
// FQ=128 rows/CTA, FN=64 keys/tile, 8 warps; warp w owns rows [16w,16w+16).
// S D-layout maps directly onto P A-layout (no shuffles).
#define FQ 128
#define FN 64
#define QLDH 104
#define FLASH_SMEM ((FQ*QLDH + 2*FN*QLDH)*2)   // 53248 B

__global__ __launch_bounds__(256, 2)
void flash_k(const half* __restrict__ qh, const half* __restrict__ kh,
             const half* __restrict__ vh, half* __restrict__ attn, float iscale)
{
    const int zi = blockIdx.y;
    const int iT = (int)gridDim.x - 1 - (int)blockIdx.x;  // heavy tiles first
    const int i0 = iT * FQ;
    const int tid = threadIdx.x;
    const int wid = tid >> 5;
    const int lane = tid & 31;
    const int g = lane >> 2;
    const int t = lane & 3;

    const half* Qp = qh + (long)zi * CS * CDP;
    const half* Kp = kh + (long)zi * CS * CDP;
    const half* Vp = vh + (long)zi * CS * CDP;

    extern __shared__ __align__(16) half smh[];
    half* Qs = smh;                   // [128][104]
    half* Ks = smh + FQ * QLDH;       // [64][104]
    half* Vs = Ks + FN * QLDH;        // [64][104]

    // Q tile: 96 halfs/row = 12 chunks of 8
    for (int tt = tid; tt < FQ * 12; tt += 256) {
        int r = tt / 12, c8 = (tt % 12) * 8;
        cp_async16(&Qs[r * QLDH + c8], Qp + (long)(i0 + r) * CDP + c8, (i0 + r) < CS);
    }
    cp_commit();

    float oacc[12][4];
    #pragma unroll
    for (int n = 0; n < 12; n++)
        #pragma unroll
        for (int s = 0; s < 4; s++) oacc[n][s] = 0.f;
    float m0 = -1e30f, m1 = -1e30f, l0 = 0.f, l1 = 0.f;

    const int rw = wid * 16;
    const int row0 = i0 + rw + g;
    const int row1 = row0 + 8;
    const int jn = (min(CS, i0 + FQ) + FN - 1) / FN;

    asm volatile("cp.async.wait_group 0;\n");
    __syncthreads();

    for (int j = 0; j < jn; j++) {
        const int j0 = j * FN;
        __syncthreads();
        for (int tt = tid; tt < FN * 12; tt += 256) {
            int r = tt / 12, c8 = (tt % 12) * 8;
            cp_async16(&Ks[r * QLDH + c8], Kp + (long)(j0 + r) * CDP + c8, (j0 + r) < CS);
        }
        cp_commit();
        for (int tt = tid; tt < FN * 12; tt += 256) {
            int r = tt / 12, c8 = (tt % 12) * 8;
            cp_async16(&Vs[r * QLDH + c8], Vp + (long)(j0 + r) * CDP + c8, (j0 + r) < CS);
        }
        cp_commit();
        asm volatile("cp.async.wait_group 1;\n");   // K ready, V flying
        __syncthreads();

        const bool active = (j0 <= i0 + rw + 15);
        float sacc[8][4];

        if (active) {
            #pragma unroll
            for (int n = 0; n < 8; n++)
                #pragma unroll
                for (int s = 0; s < 4; s++) sacc[n][s] = 0.f;

            // ---- S = Q K^T  (6 k-steps of 16) ----
            #pragma unroll
            for (int kf = 0; kf < 6; kf++) {
                const int kc = kf * 16;
                unsigned a0 = *reinterpret_cast<const unsigned*>(&Qs[(rw + g)     * QLDH + kc + 2 * t]);
                unsigned a1 = *reinterpret_cast<const unsigned*>(&Qs[(rw + g + 8) * QLDH + kc + 2 * t]);
                unsigned a2 = *reinterpret_cast<const unsigned*>(&Qs[(rw + g)     * QLDH + kc + 2 * t + 8]);
                unsigned a3 = *reinterpret_cast<const unsigned*>(&Qs[(rw + g + 8) * QLDH + kc + 2 * t + 8]);
                #pragma unroll
                for (int nf = 0; nf < 8; nf++) {
                    unsigned b0 = *reinterpret_cast<const unsigned*>(&Ks[(nf * 8 + g) * QLDH + kc + 2 * t]);
                    unsigned b1 = *reinterpret_cast<const unsigned*>(&Ks[(nf * 8 + g) * QLDH + kc + 2 * t + 8]);
                    mma_f16(sacc[nf], a0, a1, a2, a3, b0, b1);
                }
            }

            // ---- online softmax (registers + group shuffles) ----
            float rmax0 = -1e30f, rmax1 = -1e30f;
            #pragma unroll
            for (int nf = 0; nf < 8; nf++) {
                const int c0 = j0 + nf * 8 + 2 * t;
                float s0 = sacc[nf][0] * iscale; if (c0     > row0) s0 = -1e30f;
                float s1 = sacc[nf][1] * iscale; if (c0 + 1 > row0) s1 = -1e30f;
                float s2 = sacc[nf][2] * iscale; if (c0     > row1) s2 = -1e30f;
                float s3 = sacc[nf][3] * iscale; if (c0 + 1 > row1) s3 = -1e30f;
                sacc[nf][0] = s0; sacc[nf][1] = s1; sacc[nf][2] = s2; sacc[nf][3] = s3;
                rmax0 = fmaxf(rmax0, fmaxf(s0, s1));
                rmax1 = fmaxf(rmax1, fmaxf(s2, s3));
            }
            rmax0 = fmaxf(rmax0, __shfl_xor_sync(0xffffffffu, rmax0, 1));
            rmax0 = fmaxf(rmax0, __shfl_xor_sync(0xffffffffu, rmax0, 2));
            rmax1 = fmaxf(rmax1, __shfl_xor_sync(0xffffffffu, rmax1, 1));
            rmax1 = fmaxf(rmax1, __shfl_xor_sync(0xffffffffu, rmax1, 2));

            const float mn0 = fmaxf(m0, rmax0);
            const float mn1 = fmaxf(m1, rmax1);
            const float al0 = __expf(m0 - mn0);
            const float al1 = __expf(m1 - mn1);
            float ps0 = 0.f, ps1 = 0.f;
            #pragma unroll
            for (int nf = 0; nf < 8; nf++) {
                // round P to fp16 first so l matches what PV consumes
                float p0 = __half2float(__float2half_rn(__expf(sacc[nf][0] - mn0)));
                float p1 = __half2float(__float2half_rn(__expf(sacc[nf][1] - mn0)));
                float p2 = __half2float(__float2half_rn(__expf(sacc[nf][2] - mn1)));
                float p3 = __half2float(__float2half_rn(__expf(sacc[nf][3] - mn1)));
                sacc[nf][0] = p0; sacc[nf][1] = p1; sacc[nf][2] = p2; sacc[nf][3] = p3;
                ps0 += p0 + p1; ps1 += p2 + p3;
            }
            ps0 += __shfl_xor_sync(0xffffffffu, ps0, 1);
            ps0 += __shfl_xor_sync(0xffffffffu, ps0, 2);
            ps1 += __shfl_xor_sync(0xffffffffu, ps1, 1);
            ps1 += __shfl_xor_sync(0xffffffffu, ps1, 2);
            l0 = l0 * al0 + ps0;  m0 = mn0;
            l1 = l1 * al1 + ps1;  m1 = mn1;

            #pragma unroll
            for (int n = 0; n < 12; n++) {
                oacc[n][0] *= al0; oacc[n][1] *= al0;
                oacc[n][2] *= al1; oacc[n][3] *= al1;
            }
        }

        asm volatile("cp.async.wait_group 0;\n");   // V ready
        __syncthreads();

        if (active) {
            // ---- O += P V : S D-layout == P A-layout (pack, no shuffles) ----
            #pragma unroll
            for (int kf = 0; kf < 4; kf++) {        // 64 keys / 16
                const int kc = kf * 16;
                unsigned a0 = __float_as_uint(0.f), a1, a2, a3;
                a0 = *reinterpret_cast<unsigned*>(
                    &(__half2_raw&)(half2&)*(half2[1]){__floats2half2_rn(sacc[2*kf][0],   sacc[2*kf][1])});
                // (direct pack below; the above is replaced for clarity)
                half2 h0 = __floats2half2_rn(sacc[2*kf][0],     sacc[2*kf][1]);
                half2 h1 = __floats2half2_rn(sacc[2*kf][2],     sacc[2*kf][3]);
                half2 h2 = __floats2half2_rn(sacc[2*kf + 1][0], sacc[2*kf + 1][1]);
                half2 h3 = __floats2half2_rn(sacc[2*kf + 1][2], sacc[2*kf + 1][3]);
                a0 = *reinterpret_cast<unsigned*>(&h0);
                a1 = *reinterpret_cast<unsigned*>(&h1);
                a2 = *reinterpret_cast<unsigned*>(&h2);
                a3 = *reinterpret_cast<unsigned*>(&h3);
                #pragma unroll
                for (int nf = 0; nf < 12; nf++) {
                    half2 bb0 = __halves2half2(Vs[(kc + 2 * t)     * QLDH + nf * 8 + g],
                                               Vs[(kc + 2 * t + 1) * QLDH + nf * 8 + g]);
                    half2 bb1 = __halves2half2(Vs[(kc + 2 * t + 8) * QLDH + nf * 8 + g],
                                               Vs[(kc + 2 * t + 9) * QLDH + nf * 8 + g]);
                    mma_f16(oacc[nf],
                            a0, a1, a2, a3,
                            *reinterpret_cast<unsigned*>(&bb0),
                            *reinterpret_cast<unsigned*>(&bb1));
                }
            }
        }
    }

    const int b = zi / CH, h = zi - b * CH;
    const float il0 = (l0 > 0.f) ? 1.f / l0 : 0.f;
    const float il1 = (l1 > 0.f) ? 1.f / l1 : 0.f;
    #pragma unroll
    for (int nf = 0; nf < 12; nf++) {
        const int c0 = nf * 8 + 2 * t;
        if (c0 < CDK) {
            if (row0 < CS) {
                half2 v = __floats2half2_rn(oacc[nf][0] * il0, oacc[nf][1] * il0);
                *reinterpret_cast<half2*>(&attn[((long)b * CS + row0) * CD + h * CDK + c0]) = v;
            }
            if (row1 < CS) {
                half2 v = __floats2half2_rn(oacc[nf][2] * il1, oacc[nf][3] * il1);
                *reinterpret_cast<half2*>(&attn[((long)b * CS + row1) * CD + h * CDK + c0]) = v;
            }
        }
    }
}

// ---------------- f32 -> fp16 convert copy ----------------
__global__ __launch_bounds__(256)
void cvt_half_k(const float* __restrict__ s, half* __restrict__ d, int n4)
{
    int i = blockIdx.x * 256 + threadIdx.x;
    if (i < n4) {
        float4 v = reinterpret_cast<const float4*>(s)[i];
        half2* p = reinterpret_cast<half2*>(d + (size_t)i * 4);
        p[0] = __floats2half2_rn(v.x, v.y);
        p[1] = __floats2half2_rn(v.z, v.w);
    }
}

// ---------------- pack Wq|Wk|Wv -> fp16 [1080][3240] ----------------
__global__ __launch_bounds__(256)
void pack_qkv_k(const float* __restrict__ Wq, const float* __restrict__ Wk,
                const float* __restrict__ Wv,
                const float* __restrict__ bq, const float* __restrict__ bk,
                const float* __restrict__ bv,
                half* __restrict__ W, float* __restrict__ b)
{
    const int NW4 = CD * (CD / 4);
    long idx = (long)blockIdx.x * 256 + threadIdx.x;
    if (idx < NW4) {
        int r = (int)(idx / (CD / 4));
        int c = (int)(idx % (CD / 4)) * 4;
        float4 vq = *reinterpret_cast<const float4*>(Wq + (long)r * CD + c);
        float4 vk = *reinterpret_cast<const float4*>(Wk + (long)r * CD + c);
        float4 vv = *reinterpret_cast<const float4*>(Wv + (long)r * CD + c);
        half2* pq = reinterpret_cast<half2*>(W + (long)r * CFF + c);
        half2* pk = reinterpret_cast<half2*>(W + (long)r * CFF + CD + c);
        half2* pv = reinterpret_cast<half2*>(W + (long)r * CFF + 2 * CD + c);
        pq[0] = __floats2half2_rn(vq.x, vq.y); pq[1] = __floats2half2_rn(vq.z, vq.w);
        pk[0] = __floats2half2_rn(vk.x, vk.y); pk[1] = __floats2half2_rn(vk.z, vk.w);
        pv[0] = __floats2half2_rn(vv.x, vv.y); pv[1] = __floats2half2_rn(vv.z, vv.w);
    } else if (idx < NW4 + CD / 4) {
        int c = (int)(idx - NW4) * 4;
        *reinterpret_cast<float4*>(b + c)          = *reinterpret_cast<const float4*>(bq + c);
        *reinterpret_cast<float4*>(b + CD + c)     = *reinterpret_cast<const float4*>(bk + c);
        *reinterpret_cast<float4*>(b + 2 * CD + c) = *reinterpret_cast<const float4*>(bv + c);
    }
}

// ---------------- layernorm -> fp16 output ----------------
__global__ __launch_bounds__(256)
void ln_k(const float* __restrict__ x, const float* __restrict__ g,
          const float* __restrict__ b, half* __restrict__ y)
{
    const long row = blockIdx.x;
    const float* xr = x + row * CD;
    half* yr = y + row * CD;

    float s = 0.f, s2 = 0.f;
    for (int i = threadIdx.x; i < CD; i += 256) {
        float v = xr[i]; s += v; s2 += v * v;
    }
    __shared__ float rs[8], rs2[8];
    __shared__ float bm, br;
    #pragma unroll
    for (int o = 16; o; o >>= 1) {
        s  += __shfl_xor_sync(0xffffffffu, s,  o);
        s2 += __shfl_xor_sync(0xffffffffu, s2, o);
    }
    if ((threadIdx.x & 31) == 0) { rs[threadIdx.x >> 5] = s; rs2[threadIdx.x >> 5] = s2; }
    __syncthreads();
    if (threadIdx.x < 8) {
        float a = rs[threadIdx.x], a2 = rs2[threadIdx.x];
        #pragma unroll
        for (int o = 4; o; o >>= 1) {
            a  += __shfl_xor_sync(0xffu, a,  o);
            a2 += __shfl_xor_sync(0xffu, a2, o);
        }
        if (threadIdx.x == 0) {
            float mean = a / CD;
            float var  = a2 / CD - mean * mean;
            bm = mean;
            br = rsqrtf(var + 1e-5f);
        }
    }
    __syncthreads();
    const float mean = bm, rstd = br;
    for (int i = threadIdx.x; i < CD; i += 256)
        yr[i] = __float2half((xr[i] - mean) * rstd * g[i] + b[i]);
}

// -------- RoPE + repack from fp16 fused QKV to fp16 [B*H, S, 96] ------------
__global__ __launch_bounds__(256)
void rope_repack_k(const half* __restrict__ qkv,
                   const float* __restrict__ ct, const float* __restrict__ st,
                   half* __restrict__ qh, half* __restrict__ kh,
                   half* __restrict__ vh)
{
    const long total = (long)CB * CH * CS * 48;
    long idx = (long)blockIdx.x * 256 + threadIdx.x;
    if (idx >= total) return;
    const int d = (int)(idx % 48);  idx /= 48;
    const int s = (int)(idx % CS);  idx /= CS;
    const int h = (int)(idx % CH);
    const int b = (int)(idx / CH);

    const long src = ((long)b * CS + s) * CFF + h * CDK;
    const long dst = (((long)b * CH + h) * CS + s) * CDP;

    if (d < 45) {
        const float c1 = ct[s * CDK + d],      s1 = st[s * CDK + d];
        const float c2 = ct[s * CDK + d + 45], s2 = st[s * CDK + d + 45];
        float q1 = __half2float(qkv[src + d]),      q2 = __half2float(qkv[src + d + 45]);
        qh[dst + d]      = __float2half(q1 * c1 - q2 * s1);
        qh[dst + d + 45] = __float2half(q2 * c2 + q1 * s2);
        float k1 = __half2float(qkv[src + CD + d]), k2 = __half2float(qkv[src + CD + d + 45]);
        kh[dst + d]      = __float2half(k1 * c1 - k2 * s1);
        kh[dst + d + 45] = __float2half(k2 * c2 + k1 * s2);
        vh[dst + d]      = qkv[src + 2 * CD + d];
        vh[dst + d + 45] = qkv[src + 2 * CD + d + 45];
    } else {
        const int p = 90 + 2 * (d - 45);
        qh[dst + p] = __float2half(0.f); qh[dst + p + 1] = __float2half(0.f);
        kh[dst + p] = __float2half(0.f); kh[dst + p + 1] = __float2half(0.f);
        vh[dst + p] = __float2half(0.f); vh[dst + p + 1] = __float2half(0.f);
    }
}

// ---------------- host launch ----------------
extern "C" void kernel_launch(void* const* d_in, const int* in_sizes, int n_in,
                              void* d_out, int out_size)
{
    const float* x    = (const float*)d_in[0];
    const float* Wq   = (const float*)d_in[2];
    const float* bq   = (const float*)d_in[3];
    const float* Wk   = (const float*)d_in[4];
    const float* bk   = (const float*)d_in[5];
    const float* Wv   = (const float*)d_in[6];
    const float* bv   = (const float*)d_in[7];
    const float* Wo   = (const float*)d_in[8];
    const float* bo   = (const float*)d_in[9];
    const float* W1   = (const float*)d_in[10];
    const float* b1   = (const float*)d_in[11];
    const float* W2   = (const float*)d_in[12];
    const float* b2   = (const float*)d_in[13];
    const float* W3   = (const float*)d_in[14];
    const float* b3   = (const float*)d_in[15];
    const float* ln1g = (const float*)d_in[16];
    const float* ln1b = (const float*)d_in[17];
    const float* ln2g = (const float*)d_in[18];
    const float* ln2b = (const float*)d_in[19];
    const float* rc   = (const float*)d_in[20];
    const float* rs   = (const float*)d_in[21];
    float* out = (float*)d_out;

    half *x2h, *qkvh, *h1h, *attnh, *wqkvh, *wrh, *qhh, *khh, *vhh;
    float *res, *bqkv;
    cudaGetSymbolAddress((void**)&x2h,   g_x2h);
    cudaGetSymbolAddress((void**)&qkvh,  g_qkvh);
    cudaGetSymbolAddress((void**)&h1h,   g_h1h);
    cudaGetSymbolAddress((void**)&attnh, g_attnh);
    cudaGetSymbolAddress((void**)&qhh,   g_qhh);
    cudaGetSymbolAddress((void**)&khh,   g_khh);
    cudaGetSymbolAddress((void**)&vhh,   g_vhh);
    cudaGetSymbolAddress((void**)&res,   g_res);
    cudaGetSymbolAddress((void**)&wqkvh, g_wqkvh);
    cudaGetSymbolAddress((void**)&bqkv,  g_bqkv);
    cudaGetSymbolAddress((void**)&wrh,   g_wrh);

    cudaFuncSetAttribute((const void*)gemm_h<EPI_BIAS, half, float>,
                         cudaFuncAttributeMaxDynamicSharedMemorySize, SMEM_BYTES);
    cudaFuncSetAttribute((const void*)gemm_h<EPI_BIAS_RES, float, float>,
                         cudaFuncAttributeMaxDynamicSharedMemorySize, SMEM_BYTES);
    cudaFuncSetAttribute((const void*)gemm_h<EPI_SWIGLU, half, half>,
                         cudaFuncAttributeMaxDynamicSharedMemorySize, SMEM_BYTES);
    cudaFuncSetAttribute((const void*)flash_k,
                         cudaFuncAttributeMaxDynamicSharedMemorySize, FLASH_SMEM);

    const float iscale = 1.f / sqrtf((float)CDK);

    // 0) fp16 weights + pack QKV
    cvt_half_k<<<(291600 + 255) / 256, 256>>>(Wo, wrh + WR_WO, 291600);
    cvt_half_k<<<(874800 + 255) / 256, 256>>>(W1, wrh + WR_W1, 874800);
    cvt_half_k<<<(874800 + 255) / 256, 256>>>(W3, wrh + WR_W3, 874800);
    cvt_half_k<<<(874800 + 255) / 256, 256>>>(W2, wrh + WR_W2, 874800);
    {
        int total = CD * (CD / 4) + CD / 4;
        pack_qkv_k<<<(total + 255) / 256, 256>>>(Wq, Wk, Wv, bq, bk, bv, wqkvh, bqkv);
    }

    // 1) LN1 -> fp16
    ln_k<<<CBS, 256>>>(x, ln1g, ln1b, x2h);

    // 2) fused QKV projection
    dim3 gQKV((CFF + 127) / 128, (CBS + 127) / 128, 1);
    gemm_h<EPI_BIAS, half, float><<<gQKV, 256, SMEM_BYTES>>>(
        x2h, CD, wqkvh, CFF, qkvh, CFF, bqkv, (const float*)nullptr, 0, CBS, CFF, CD);

    // 3) RoPE + repack (fp16 out)
    {
        long total = (long)CB * CH * CS * 48;
        rope_repack_k<<<(unsigned)((total + 255) / 256), 256>>>(qkvh, rc, rs, qhh, khh, vhh);
    }

    // 4) flash attention (fp16 mma), output fp16
    {
        dim3 g((CS + FQ - 1) / FQ, CB * CH);
        flash_k<<<g, 256, FLASH_SMEM>>>(qhh, khh, vhh, attnh, iscale);
    }

    // 5) O-projection + bias + residual(x) -> f32 res
    dim3 gD((CD + 127) / 128, (CBS + 127) / 128, 1);
    gemm_h<EPI_BIAS_RES, float, float><<<gD, 256, SMEM_BYTES>>>(
        attnh, CD, wrh + WR_WO, CD, res, CD, bo, x, CD, CBS, CD, CD);

    // 6) LN2 -> fp16
    ln_k<<<CBS, 256>>>(res, ln2g, ln2b, x2h);

    // 7) h1 = x2@W1 + b1
    dim3 gF((CFF + 127) / 128, (CBS + 127) / 128, 1);
    gemm_h<EPI_BIAS, half, float><<<gF, 256, SMEM_BYTES>>>(
        x2h, CD, wrh + WR_W1, CFF, h1h, CFF, b1, (const float*)nullptr, 0, CBS, CFF, CD);

    // 8) h1 = silu(h1) * (x2@W3 + b3)
    gemm_h<EPI_SWIGLU, half, half><<<gF, 256, SMEM_BYTES>>>(
        x2h, CD, wrh + WR_W3, CFF, h1h, CFF, b3, h1h, CFF, CBS, CFF, CD);

    // 9) out = res + h1@W2 + b2
    gemm_h<EPI_BIAS_RES, float, float><<<gD, 256, SMEM_BYTES>>>(
        h1h, CFF, wrh + WR_W2, CD, out, CD, b2, res, CD, CBS, CD, CFF);
}